// round 10
// baseline (speedup 1.0000x reference)
#include <cuda_runtime.h>
#include <cuda_fp16.h>
#include <math.h>
#include <stdint.h>

// Problem constants
#define Bq    4
#define Lq    4096
#define Dq    1024
#define Hq    16
#define DHq   64
#define MTOK  (Bq*Lq)      // 16384
#define NQKV  (3*Dq)       // 3072
#define RMSEPS 1.1920929e-07f
#define EPSLIN 1e-06f
#define NCHUNK 8

// Scratch (device globals — no allocation allowed)
__device__ __align__(256) __half g_qkvh[(size_t)MTOK * NQKV];   // fp16 qkv / qf kf v
__device__ __align__(256) float g_vkp [NCHUNK * 64 * 65 * DHq];
__device__ __align__(256) float g_vk  [64 * 65 * DHq];
__device__ __align__(256) float g_y   [(size_t)MTOK * Dq];
__device__ __align__(256) float g_cos [Lq * 32];
__device__ __align__(256) float g_sin [Lq * 32];
// fp16 operands
__device__ __align__(256) __half g_xh [(size_t)MTOK * Dq];
__device__ __align__(256) __half g_ah [(size_t)MTOK * Dq];   // attn in fp16 (gemm2 A)
__device__ __align__(256) __half g_wh1[(size_t)NQKV * Dq];
__device__ __align__(256) __half g_wh2[(size_t)Dq * Dq];

// ---------------------------------------------------------------------------
__device__ __forceinline__ uint32_t smem_u32(const void* p) {
    uint32_t a;
    asm("{ .reg .u64 t; cvta.to.shared.u64 t, %1; cvt.u32.u64 %0, t; }" : "=r"(a) : "l"(p));
    return a;
}
__device__ __forceinline__ void cp_async16(uint32_t dst, const void* src) {
    asm volatile("cp.async.cg.shared.global [%0], [%1], 16;" :: "r"(dst), "l"(src));
}
#define CP_COMMIT() asm volatile("cp.async.commit_group;" ::: "memory")
template <int N>
__device__ __forceinline__ void cp_wait() {
    asm volatile("cp.async.wait_group %0;" :: "n"(N) : "memory");
}
__device__ __forceinline__ void ldm_x4(uint32_t* r, uint32_t addr) {
    asm volatile("ldmatrix.sync.aligned.m8n8.x4.shared.b16 {%0,%1,%2,%3}, [%4];"
                 : "=r"(r[0]), "=r"(r[1]), "=r"(r[2]), "=r"(r[3]) : "r"(addr));
}
__device__ __forceinline__ void mma_f16(float* c, const uint32_t* a, const uint32_t* b) {
    asm volatile(
        "mma.sync.aligned.m16n8k16.row.col.f32.f16.f16.f32 "
        "{%0,%1,%2,%3}, {%4,%5,%6,%7}, {%8,%9}, {%0,%1,%2,%3};"
        : "+f"(c[0]), "+f"(c[1]), "+f"(c[2]), "+f"(c[3])
        : "r"(a[0]), "r"(a[1]), "r"(a[2]), "r"(a[3]), "r"(b[0]), "r"(b[1]));
}

// ---------------------------------------------------------------------------
// K0: RoPE tables
// ---------------------------------------------------------------------------
__global__ void rope_tables_k() {
    int idx = blockIdx.x * blockDim.x + threadIdx.x;
    if (idx >= Lq * 32) return;
    int l = idx >> 5, j = idx & 31;
    float inv_freq = expf(-(float)j * (9.210340371976184f / 32.0f));
    float ang = (float)l * inv_freq;
    g_cos[idx] = cosf(ang);
    g_sin[idx] = sinf(ang);
}

// fp32 -> fp16
__global__ __launch_bounds__(256) void to_half_k(
    const float* __restrict__ s, __half* __restrict__ d, int n4)
{
    int i = blockIdx.x * 256 + threadIdx.x;
    if (i >= n4) return;
    float4 v = ((const float4*)s)[i];
    __half2 h0 = __floats2half2_rn(v.x, v.y);
    __half2 h1 = __floats2half2_rn(v.z, v.w);
    ((__half2*)d)[2*i]   = h0;
    ((__half2*)d)[2*i+1] = h1;
}

// ---------------------------------------------------------------------------
// HMMA GEMM: C[m,n] = sum_k A[m,k]*B[n,k] + bias[n], K = 1024. Templated out type.
// fp16 MMA, fp32 acc. Tile 128x128, 8 warps (4m x 2n). 4-stage cp.async.
// ---------------------------------------------------------------------------
#define BKS     32
#define NSLAB   32                  // 1024/32
#define PITCH   80                  // bytes per row (64B data + 16B pad)
#define TILEB   (128 * PITCH)       // 10240
#define OFF_B   TILEB
#define STAGE   (2 * TILEB)         // 20480
#define NSTG    4

template <typename OutT>
__global__ __launch_bounds__(256, 2)
void gemm_hmma3_k(const __half* __restrict__ A, const __half* __restrict__ B,
                  const float* __restrict__ bias, OutT* __restrict__ C, int N)
{
    extern __shared__ __align__(16) char sm[];
    const uint32_t smb = smem_u32(sm);
    const int tid  = threadIdx.x;
    const int wid  = tid >> 5, lane = tid & 31;
    const int wm   = wid & 3, wn = wid >> 2;
    const int g    = lane >> 2, t = lane & 3;
    const int m0   = blockIdx.y * 128;
    const int n0   = blockIdx.x * 128;

    float acc[2][8][4];
#pragma unroll
    for (int mf = 0; mf < 2; ++mf)
#pragma unroll
        for (int nf = 0; nf < 8; ++nf)
#pragma unroll
            for (int e = 0; e < 4; ++e) acc[mf][nf][e] = 0.0f;

    const int crow = tid >> 2;
    const int c16  = tid & 3;
    auto load_slab = [&](int ks, int st) {
        uint32_t base = smb + st * STAGE;
#pragma unroll
        for (int j = 0; j < 2; ++j) {
            int row = crow + j * 64;
            uint32_t d = base + row * PITCH + c16 * 16;
            cp_async16(d,         A + (size_t)(m0 + row) * 1024 + ks * BKS + c16 * 8);
            cp_async16(d + OFF_B, B + (size_t)(n0 + row) * 1024 + ks * BKS + c16 * 8);
        }
        CP_COMMIT();
    };

    const int quad = lane >> 3, r8 = lane & 7;
    const uint32_t aoff = (uint32_t)((wm * 32 + (quad & 1) * 8 + r8) * PITCH + (quad >> 1) * 16);
    const uint32_t boff = (uint32_t)((wn * 64 + (quad >> 1) * 8 + r8) * PITCH + (quad & 1) * 16);

    load_slab(0, 0);
    load_slab(1, 1);
    load_slab(2, 2);

#pragma unroll 1
    for (int i = 0; i < NSLAB; ++i) {
        cp_wait<2>();
        __syncthreads();
        if (i + 3 < NSLAB) load_slab(i + 3, (i + 3) & 3);
        else CP_COMMIT();
        const uint32_t st = smb + (uint32_t)(i & 3) * STAGE;
#pragma unroll
        for (int kk = 0; kk < 2; ++kk) {
            uint32_t a[2][4];
            ldm_x4(a[0], st + aoff + kk * 32);
            ldm_x4(a[1], st + aoff + kk * 32 + 16 * PITCH);
            const uint32_t bb = st + OFF_B + boff + kk * 32;
#pragma unroll
            for (int nf2 = 0; nf2 < 4; ++nf2) {
                uint32_t b[4];
                ldm_x4(b, bb + nf2 * (16 * PITCH));
                mma_f16(acc[0][2*nf2],   a[0], b);
                mma_f16(acc[0][2*nf2+1], a[0], b + 2);
                mma_f16(acc[1][2*nf2],   a[1], b);
                mma_f16(acc[1][2*nf2+1], a[1], b + 2);
            }
        }
    }

#pragma unroll
    for (int mf = 0; mf < 2; ++mf) {
        int row = m0 + wm * 32 + mf * 16 + g;
#pragma unroll
        for (int nf = 0; nf < 8; ++nf) {
            int col = n0 + wn * 64 + nf * 8 + 2 * t;
            float b0 = bias[col], b1 = bias[col + 1];
            float v00 = acc[mf][nf][0] + b0, v01 = acc[mf][nf][1] + b1;
            float v10 = acc[mf][nf][2] + b0, v11 = acc[mf][nf][3] + b1;
            if constexpr (sizeof(OutT) == 2) {
                *(__half2*)((__half*)C + (size_t)row * N + col)       = __floats2half2_rn(v00, v01);
                *(__half2*)((__half*)C + (size_t)(row + 8) * N + col) = __floats2half2_rn(v10, v11);
            } else {
                *(float2*)((float*)C + (size_t)row * N + col)       = make_float2(v00, v01);
                *(float2*)((float*)C + (size_t)(row + 8) * N + col) = make_float2(v10, v11);
            }
        }
    }
}

// ---------------------------------------------------------------------------
// K2: per-token rmsnorm(q), rmsnorm(k), RoPE, ReLU — in place in g_qkvh (fp16).
// ---------------------------------------------------------------------------
__global__ __launch_bounds__(256) void qk_prep_k(const float* __restrict__ gq,
                                                 const float* __restrict__ gk)
{
    const int t = blockIdx.x;
    const int l = t & (Lq - 1);
    const int tid = threadIdx.x;
    __half* row = g_qkvh + (size_t)t * NQKV;
    uint2 qr = *(uint2*)(row + tid * 4);
    uint2 kr = *(uint2*)(row + Dq + tid * 4);
    float2 q01 = __half22float2(*(__half2*)&qr.x);
    float2 q23 = __half22float2(*(__half2*)&qr.y);
    float2 k01 = __half22float2(*(__half2*)&kr.x);
    float2 k23 = __half22float2(*(__half2*)&kr.y);
    float qe[4] = {q01.x, q01.y, q23.x, q23.y};
    float ke[4] = {k01.x, k01.y, k23.x, k23.y};
    float sq = qe[0]*qe[0] + qe[1]*qe[1] + qe[2]*qe[2] + qe[3]*qe[3];
    float sk = ke[0]*ke[0] + ke[1]*ke[1] + ke[2]*ke[2] + ke[3]*ke[3];
#pragma unroll
    for (int o = 16; o > 0; o >>= 1) {
        sq += __shfl_xor_sync(0xffffffffu, sq, o);
        sk += __shfl_xor_sync(0xffffffffu, sk, o);
    }
    __shared__ float wq[8], wk[8];
    __shared__ float bq, bk;
    const int warp = tid >> 5, lane = tid & 31;
    if (lane == 0) { wq[warp] = sq; wk[warp] = sk; }
    __syncthreads();
    if (tid == 0) {
        float aq = 0.0f, ak = 0.0f;
#pragma unroll
        for (int i = 0; i < 8; ++i) { aq += wq[i]; ak += wk[i]; }
        bq = rsqrtf(aq * (1.0f / 1024.0f) + RMSEPS);
        bk = rsqrtf(ak * (1.0f / 1024.0f) + RMSEPS);
    }
    __syncthreads();
    const float scq = bq, sck = bk;
    const int c0 = tid * 4;
#pragma unroll
    for (int i = 0; i < 4; ++i) {
        qe[i] *= scq * gq[c0 + i];
        ke[i] *= sck * gk[c0 + i];
    }
#pragma unroll
    for (int p = 0; p < 2; ++p) {
        int d = (c0 + 2 * p) & 63;
        int j = d >> 1;
        float c = g_cos[l * 32 + j];
        float s = g_sin[l * 32 + j];
        float q0 = qe[2*p], q1 = qe[2*p + 1];
        qe[2*p]     = q0 * c - q1 * s;
        qe[2*p + 1] = q0 * s + q1 * c;
        float k0 = ke[2*p], k1 = ke[2*p + 1];
        ke[2*p]     = k0 * c - k1 * s;
        ke[2*p + 1] = k0 * s + k1 * c;
    }
    uint2 qo, ko;
    *(__half2*)&qo.x = __floats2half2_rn(fmaxf(qe[0],0.f), fmaxf(qe[1],0.f));
    *(__half2*)&qo.y = __floats2half2_rn(fmaxf(qe[2],0.f), fmaxf(qe[3],0.f));
    *(__half2*)&ko.x = __floats2half2_rn(fmaxf(ke[0],0.f), fmaxf(ke[1],0.f));
    *(__half2*)&ko.y = __floats2half2_rn(fmaxf(ke[2],0.f), fmaxf(ke[3],0.f));
    *(uint2*)(row + tid * 4)      = qo;
    *(uint2*)(row + Dq + tid * 4) = ko;
}

// ---------------------------------------------------------------------------
// K3: vk partials, register-tiled. CTA = (b*H+h, Lchunk of 512 tokens).
// ---------------------------------------------------------------------------
__global__ __launch_bounds__(256) void vk_accum_k() {
    const int bh = blockIdx.x;
    const int chunk = blockIdx.y;       // 0..NCHUNK-1
    const int b = bh >> 4, h = bh & 15;
    const int tid = threadIdx.x;
    __shared__ __align__(16) float kf_s[32 * 64];
    __shared__ __align__(16) float vp_s[32 * 64];
    const int pq = tid >> 4;
    const int dq = tid & 15;
    float acc[4][4];
    float den[4] = {0.f, 0.f, 0.f, 0.f};
#pragma unroll
    for (int i = 0; i < 4; ++i)
#pragma unroll
        for (int j = 0; j < 4; ++j) acc[i][j] = 0.0f;

    const int tok0 = b * Lq + chunk * (Lq / NCHUNK);
    const int lr  = tid >> 3;           // 0..31 row
    const int lc8 = (tid & 7) << 3;     // 0..56 col (8 halves)
    for (int sub = 0; sub < (Lq / NCHUNK) / 32; ++sub) {
        const int tbase = tok0 + sub * 32;
        {
            const __half* src = g_qkvh + (size_t)(tbase + lr) * NQKV + h * DHq + lc8;
            uint4 kraw = *(const uint4*)(src + Dq);
            uint4 vraw = *(const uint4*)(src + 2 * Dq);
            float2 f0 = __half22float2(*(__half2*)&kraw.x);
            float2 f1 = __half22float2(*(__half2*)&kraw.y);
            float2 f2 = __half22float2(*(__half2*)&kraw.z);
            float2 f3 = __half22float2(*(__half2*)&kraw.w);
            *(float4*)&kf_s[lr * 64 + lc8]     = make_float4(f0.x, f0.y, f1.x, f1.y);
            *(float4*)&kf_s[lr * 64 + lc8 + 4] = make_float4(f2.x, f2.y, f3.x, f3.y);
            f0 = __half22float2(*(__half2*)&vraw.x);
            f1 = __half22float2(*(__half2*)&vraw.y);
            f2 = __half22float2(*(__half2*)&vraw.z);
            f3 = __half22float2(*(__half2*)&vraw.w);
            *(float4*)&vp_s[lr * 64 + lc8]     = make_float4(f0.x, f0.y, f1.x, f1.y);
            *(float4*)&vp_s[lr * 64 + lc8 + 4] = make_float4(f2.x, f2.y, f3.x, f3.y);
        }
        __syncthreads();
#pragma unroll 8
        for (int r = 0; r < 32; ++r) {
            float4 vp = *(const float4*)&vp_s[r * 64 + pq * 4];
            float4 kf = *(const float4*)&kf_s[r * 64 + dq * 4];
            const float kfe[4] = {kf.x, kf.y, kf.z, kf.w};
            const float vpe[4] = {vp.x, vp.y, vp.z, vp.w};
#pragma unroll
            for (int i = 0; i < 4; ++i)
#pragma unroll
                for (int j = 0; j < 4; ++j)
                    acc[i][j] = fmaf(vpe[i], kfe[j], acc[i][j]);
            if (pq == 0) {
#pragma unroll
                for (int j = 0; j < 4; ++j) den[j] += kfe[j];
            }
        }
        __syncthreads();
    }
    float* dst = g_vkp + (size_t)chunk * (64 * 65 * 64) + bh * (65 * 64);
#pragma unroll
    for (int i = 0; i < 4; ++i) {
        float4 o = make_float4(acc[i][0], acc[i][1], acc[i][2], acc[i][3]);
        *(float4*)(dst + (pq * 4 + i) * 64 + dq * 4) = o;
    }
    if (pq == 0)
        *(float4*)(dst + 64 * 64 + dq * 4) = make_float4(den[0], den[1], den[2], den[3]);
}

// K4: deterministic reduce of the NCHUNK partials.
__global__ void vk_reduce_k() {
    int i = blockIdx.x * 256 + threadIdx.x;
    if (i >= 64 * 65 * 64) return;
    float s = 0.0f;
#pragma unroll
    for (int c = 0; c < NCHUNK; ++c) s += g_vkp[(size_t)c * (64 * 65 * 64) + i];
    g_vk[i] = s;
}

// ---------------------------------------------------------------------------
// K5: res = vk . qf ; attn = res[:64]/(res[64]+eps) -> fp16 into g_ah.
// ---------------------------------------------------------------------------
#define VKP 68
__global__ __launch_bounds__(256) void attn_apply_k() {
    const int bh = blockIdx.x;
    const int lt = blockIdx.y;
    const int b = bh >> 4, h = bh & 15;
    const int tid = threadIdx.x;
    __shared__ __align__(16) float qf_s[64 * 64];
    __shared__ __align__(16) float vk_s[65 * VKP];
    __shared__ float den_s[64];
#pragma unroll
    for (int ei = 0; ei < 17; ++ei) {
        int e = tid + ei * 256;
        if (e < 65 * 64) vk_s[(e >> 6) * VKP + (e & 63)] = g_vk[bh * (65 * 64) + e];
    }
    const int tok0 = b * Lq + lt * 64;
    {
        const int r = tid >> 2;            // 0..63
        const int c16 = (tid & 3) << 4;    // 0,16,32,48
        const __half* src = g_qkvh + (size_t)(tok0 + r) * NQKV + h * DHq + c16;
#pragma unroll
        for (int half8 = 0; half8 < 2; ++half8) {
            uint4 raw = *(const uint4*)(src + half8 * 8);
            float2 f0 = __half22float2(*(__half2*)&raw.x);
            float2 f1 = __half22float2(*(__half2*)&raw.y);
            float2 f2 = __half22float2(*(__half2*)&raw.z);
            float2 f3 = __half22float2(*(__half2*)&raw.w);
            *(float4*)&qf_s[r * 64 + c16 + half8 * 8]     = make_float4(f0.x, f0.y, f1.x, f1.y);
            *(float4*)&qf_s[r * 64 + c16 + half8 * 8 + 4] = make_float4(f2.x, f2.y, f3.x, f3.y);
        }
    }
    __syncthreads();
    if (tid < 64) {
        float d = 0.0f;
#pragma unroll
        for (int kk = 0; kk < 64; ++kk) {
            int k = (kk + tid) & 63;
            d = fmaf(vk_s[64 * VKP + k], qf_s[tid * 64 + k], d);
        }
        den_s[tid] = d;
    }
    __syncthreads();
    const int dd  = tid & 63;
    const int grp = tid >> 6;
    __half* outp = g_ah + (size_t)(b * Lq + lt * 64) * Dq + h * DHq + dd;
#pragma unroll 1
    for (int gi = 0; gi < 4; ++gi) {
        const int tokb = grp * 16 + gi * 4;
        float a0 = 0.f, a1 = 0.f, a2 = 0.f, a3 = 0.f;
#pragma unroll
        for (int k4 = 0; k4 < 16; ++k4) {
            float4 v  = *(const float4*)&vk_s[dd * VKP + k4 * 4];
            float4 q0 = *(const float4*)&qf_s[(tokb + 0) * 64 + k4 * 4];
            float4 q1 = *(const float4*)&qf_s[(tokb + 1) * 64 + k4 * 4];
            float4 q2 = *(const float4*)&qf_s[(tokb + 2) * 64 + k4 * 4];
            float4 q3 = *(const float4*)&qf_s[(tokb + 3) * 64 + k4 * 4];
            a0 = fmaf(v.x, q0.x, a0); a0 = fmaf(v.y, q0.y, a0);
            a0 = fmaf(v.z, q0.z, a0); a0 = fmaf(v.w, q0.w, a0);
            a1 = fmaf(v.x, q1.x, a1); a1 = fmaf(v.y, q1.y, a1);
            a1 = fmaf(v.z, q1.z, a1); a1 = fmaf(v.w, q1.w, a1);
            a2 = fmaf(v.x, q2.x, a2); a2 = fmaf(v.y, q2.y, a2);
            a2 = fmaf(v.z, q2.z, a2); a2 = fmaf(v.w, q2.w, a2);
            a3 = fmaf(v.x, q3.x, a3); a3 = fmaf(v.y, q3.y, a3);
            a3 = fmaf(v.z, q3.z, a3); a3 = fmaf(v.w, q3.w, a3);
        }
        outp[(size_t)(tokb + 0) * Dq] = __float2half_rn(a0 / (den_s[tokb + 0] + EPSLIN));
        outp[(size_t)(tokb + 1) * Dq] = __float2half_rn(a1 / (den_s[tokb + 1] + EPSLIN));
        outp[(size_t)(tokb + 2) * Dq] = __float2half_rn(a2 / (den_s[tokb + 2] + EPSLIN));
        outp[(size_t)(tokb + 3) * Dq] = __float2half_rn(a3 / (den_s[tokb + 3] + EPSLIN));
    }
}

// ---------------------------------------------------------------------------
// K7: final rmsnorm over g_y rows -> d_out
// ---------------------------------------------------------------------------
__global__ __launch_bounds__(256) void out_rms_k(const float* __restrict__ gout,
                                                 float* __restrict__ out)
{
    const int t = blockIdx.x;
    const int tid = threadIdx.x;
    const float* row = g_y + (size_t)t * Dq;
    float4 y = *(const float4*)(row + tid * 4);
    float ss = y.x*y.x + y.y*y.y + y.z*y.z + y.w*y.w;
#pragma unroll
    for (int o = 16; o > 0; o >>= 1) ss += __shfl_xor_sync(0xffffffffu, ss, o);
    __shared__ float w[8];
    __shared__ float bsc;
    if ((tid & 31) == 0) w[tid >> 5] = ss;
    __syncthreads();
    if (tid == 0) {
        float a = 0.0f;
#pragma unroll
        for (int i = 0; i < 8; ++i) a += w[i];
        bsc = rsqrtf(a * (1.0f / 1024.0f) + RMSEPS);
    }
    __syncthreads();
    const float sc = bsc;
    const int c0 = tid * 4;
    float4 o4;
    o4.x = y.x * sc * gout[c0 + 0];
    o4.y = y.y * sc * gout[c0 + 1];
    o4.z = y.z * sc * gout[c0 + 2];
    o4.w = y.w * sc * gout[c0 + 3];
    *(float4*)(out + (size_t)t * Dq + c0) = o4;
}

// ---------------------------------------------------------------------------
extern "C" void kernel_launch(void* const* d_in, const int* in_sizes, int n_in,
                              void* d_out, int out_size) {
    (void)in_sizes; (void)n_in; (void)out_size;
    const float* x    = (const float*)d_in[0];
    const float* Wqkv = (const float*)d_in[1];
    const float* bqkv = (const float*)d_in[2];
    const float* gq   = (const float*)d_in[3];
    const float* gk   = (const float*)d_in[4];
    const float* Wout = (const float*)d_in[5];
    const float* bout = (const float*)d_in[6];
    const float* gout = (const float*)d_in[7];
    float* out = (float*)d_out;

    float* y_p;
    __half *qkvh_p, *xh, *ah, *wh1, *wh2;
    cudaGetSymbolAddress((void**)&qkvh_p, g_qkvh);
    cudaGetSymbolAddress((void**)&y_p,   g_y);
    cudaGetSymbolAddress((void**)&xh,  g_xh);
    cudaGetSymbolAddress((void**)&ah,  g_ah);
    cudaGetSymbolAddress((void**)&wh1, g_wh1);
    cudaGetSymbolAddress((void**)&wh2, g_wh2);

    const int DSMEM = NSTG * STAGE;   // 81920
    cudaFuncSetAttribute(gemm_hmma3_k<__half>, cudaFuncAttributeMaxDynamicSharedMemorySize, DSMEM);
    cudaFuncSetAttribute(gemm_hmma3_k<float>,  cudaFuncAttributeMaxDynamicSharedMemorySize, DSMEM);

    rope_tables_k<<<(Lq * 32 + 255) / 256, 256>>>();                          // 0
    to_half_k<<<(MTOK * Dq / 4 + 255) / 256, 256>>>(x, xh, MTOK * Dq / 4);    // 1
    to_half_k<<<(NQKV * Dq / 4 + 255) / 256, 256>>>(Wqkv, wh1, NQKV * Dq / 4);// 2
    gemm_hmma3_k<__half><<<dim3(NQKV / 128, MTOK / 128), 256, DSMEM>>>(       // 3 (profiled slot)
        xh, wh1, bqkv, qkvh_p, NQKV);
    to_half_k<<<(Dq * Dq / 4 + 255) / 256, 256>>>(Wout, wh2, Dq * Dq / 4);    // 4
    qk_prep_k<<<MTOK, 256>>>(gq, gk);
    vk_accum_k<<<dim3(64, NCHUNK), 256>>>();
    vk_reduce_k<<<(64 * 65 * 64 + 255) / 256, 256>>>();
    attn_apply_k<<<dim3(64, 64), 256>>>();
    gemm_hmma3_k<float><<<dim3(Dq / 128, MTOK / 128), 256, DSMEM>>>(
        ah, wh2, bout, y_p, Dq);
    out_rms_k<<<MTOK, 256>>>(gout, out);
}

// round 11
// speedup vs baseline: 1.5117x; 1.5117x over previous
#include <cuda_runtime.h>
#include <cuda_fp16.h>
#include <math.h>
#include <stdint.h>

// Problem constants
#define Bq    4
#define Lq    4096
#define Dq    1024
#define Hq    16
#define DHq   64
#define MTOK  (Bq*Lq)      // 16384
#define NQKV  (3*Dq)       // 3072
#define RMSEPS 1.1920929e-07f
#define EPSLIN 1e-06f
#define NCHUNK 8

// Scratch (device globals — no allocation allowed)
__device__ __align__(256) float g_qkv [(size_t)MTOK * NQKV];   // fp32 qkv (v read later)
__device__ __align__(256) float g_vkp [NCHUNK * 64 * 65 * DHq];
__device__ __align__(256) float g_vk  [64 * 65 * DHq];
__device__ __align__(256) float g_y   [(size_t)MTOK * Dq];
__device__ __align__(256) float g_cos [Lq * 32];
__device__ __align__(256) float g_sin [Lq * 32];
// fp16 operands / intermediates
__device__ __align__(256) __half g_xh [(size_t)MTOK * Dq];
__device__ __align__(256) __half g_ah [(size_t)MTOK * Dq];    // attn in fp16 (gemm2 A)
__device__ __align__(256) __half g_wh1[(size_t)NQKV * Dq];
__device__ __align__(256) __half g_wh2[(size_t)Dq * Dq];
__device__ __align__(256) __half g_qfh[(size_t)MTOK * Dq];    // qf, head-major [bh][l][64]
__device__ __align__(256) __half g_kfh[(size_t)MTOK * Dq];    // kf, head-major [bh][l][64]

// ---------------------------------------------------------------------------
__device__ __forceinline__ uint32_t smem_u32(const void* p) {
    uint32_t a;
    asm("{ .reg .u64 t; cvta.to.shared.u64 t, %1; cvt.u32.u64 %0, t; }" : "=r"(a) : "l"(p));
    return a;
}
__device__ __forceinline__ void cp_async16(uint32_t dst, const void* src) {
    asm volatile("cp.async.cg.shared.global [%0], [%1], 16;" :: "r"(dst), "l"(src));
}
#define CP_COMMIT() asm volatile("cp.async.commit_group;" ::: "memory")
template <int N>
__device__ __forceinline__ void cp_wait() {
    asm volatile("cp.async.wait_group %0;" :: "n"(N) : "memory");
}
__device__ __forceinline__ void ldm_x4(uint32_t* r, uint32_t addr) {
    asm volatile("ldmatrix.sync.aligned.m8n8.x4.shared.b16 {%0,%1,%2,%3}, [%4];"
                 : "=r"(r[0]), "=r"(r[1]), "=r"(r[2]), "=r"(r[3]) : "r"(addr));
}
__device__ __forceinline__ void mma_f16(float* c, const uint32_t* a, const uint32_t* b) {
    asm volatile(
        "mma.sync.aligned.m16n8k16.row.col.f32.f16.f16.f32 "
        "{%0,%1,%2,%3}, {%4,%5,%6,%7}, {%8,%9}, {%0,%1,%2,%3};"
        : "+f"(c[0]), "+f"(c[1]), "+f"(c[2]), "+f"(c[3])
        : "r"(a[0]), "r"(a[1]), "r"(a[2]), "r"(a[3]), "r"(b[0]), "r"(b[1]));
}

// ---------------------------------------------------------------------------
// K0: RoPE tables
// ---------------------------------------------------------------------------
__global__ void rope_tables_k() {
    int idx = blockIdx.x * blockDim.x + threadIdx.x;
    if (idx >= Lq * 32) return;
    int l = idx >> 5, j = idx & 31;
    float inv_freq = expf(-(float)j * (9.210340371976184f / 32.0f));
    float ang = (float)l * inv_freq;
    g_cos[idx] = cosf(ang);
    g_sin[idx] = sinf(ang);
}

// fp32 -> fp16
__global__ __launch_bounds__(256) void to_half_k(
    const float* __restrict__ s, __half* __restrict__ d, int n4)
{
    int i = blockIdx.x * 256 + threadIdx.x;
    if (i >= n4) return;
    float4 v = ((const float4*)s)[i];
    __half2 h0 = __floats2half2_rn(v.x, v.y);
    __half2 h1 = __floats2half2_rn(v.z, v.w);
    ((__half2*)d)[2*i]   = h0;
    ((__half2*)d)[2*i+1] = h1;
}

// ---------------------------------------------------------------------------
// HMMA GEMM (R9-frozen): C[m,n] = sum_k A[m,k]*B[n,k] + bias[n], K = 1024.
// fp16 MMA, fp32 acc. Tile 128x128, 8 warps (4m x 2n). 4-stage cp.async.
// ---------------------------------------------------------------------------
#define BKS     32
#define NSLAB   32                  // 1024/32
#define PITCH   80                  // bytes per row (64B data + 16B pad)
#define TILEB   (128 * PITCH)       // 10240
#define OFF_B   TILEB
#define STAGE   (2 * TILEB)         // 20480
#define NSTG    4

__global__ __launch_bounds__(256, 2)
void gemm_hmma3_k(const __half* __restrict__ A, const __half* __restrict__ B,
                  const float* __restrict__ bias, float* __restrict__ C, int N)
{
    extern __shared__ __align__(16) char sm[];
    const uint32_t smb = smem_u32(sm);
    const int tid  = threadIdx.x;
    const int wid  = tid >> 5, lane = tid & 31;
    const int wm   = wid & 3, wn = wid >> 2;
    const int g    = lane >> 2, t = lane & 3;
    const int m0   = blockIdx.y * 128;
    const int n0   = blockIdx.x * 128;

    float acc[2][8][4];
#pragma unroll
    for (int mf = 0; mf < 2; ++mf)
#pragma unroll
        for (int nf = 0; nf < 8; ++nf)
#pragma unroll
            for (int e = 0; e < 4; ++e) acc[mf][nf][e] = 0.0f;

    const int crow = tid >> 2;
    const int c16  = tid & 3;
    auto load_slab = [&](int ks, int st) {
        uint32_t base = smb + st * STAGE;
#pragma unroll
        for (int j = 0; j < 2; ++j) {
            int row = crow + j * 64;
            uint32_t d = base + row * PITCH + c16 * 16;
            cp_async16(d,         A + (size_t)(m0 + row) * 1024 + ks * BKS + c16 * 8);
            cp_async16(d + OFF_B, B + (size_t)(n0 + row) * 1024 + ks * BKS + c16 * 8);
        }
        CP_COMMIT();
    };

    const int quad = lane >> 3, r8 = lane & 7;
    const uint32_t aoff = (uint32_t)((wm * 32 + (quad & 1) * 8 + r8) * PITCH + (quad >> 1) * 16);
    const uint32_t boff = (uint32_t)((wn * 64 + (quad >> 1) * 8 + r8) * PITCH + (quad & 1) * 16);

    load_slab(0, 0);
    load_slab(1, 1);
    load_slab(2, 2);

#pragma unroll 1
    for (int i = 0; i < NSLAB; ++i) {
        cp_wait<2>();
        __syncthreads();
        if (i + 3 < NSLAB) load_slab(i + 3, (i + 3) & 3);
        else CP_COMMIT();
        const uint32_t st = smb + (uint32_t)(i & 3) * STAGE;
#pragma unroll
        for (int kk = 0; kk < 2; ++kk) {
            uint32_t a[2][4];
            ldm_x4(a[0], st + aoff + kk * 32);
            ldm_x4(a[1], st + aoff + kk * 32 + 16 * PITCH);
            const uint32_t bb = st + OFF_B + boff + kk * 32;
#pragma unroll
            for (int nf2 = 0; nf2 < 4; ++nf2) {
                uint32_t b[4];
                ldm_x4(b, bb + nf2 * (16 * PITCH));
                mma_f16(acc[0][2*nf2],   a[0], b);
                mma_f16(acc[0][2*nf2+1], a[0], b + 2);
                mma_f16(acc[1][2*nf2],   a[1], b);
                mma_f16(acc[1][2*nf2+1], a[1], b + 2);
            }
        }
    }

#pragma unroll
    for (int mf = 0; mf < 2; ++mf) {
        int row = m0 + wm * 32 + mf * 16 + g;
#pragma unroll
        for (int nf = 0; nf < 8; ++nf) {
            int col = n0 + wn * 64 + nf * 8 + 2 * t;
            float b0 = bias[col], b1 = bias[col + 1];
            float2 o0 = make_float2(acc[mf][nf][0] + b0, acc[mf][nf][1] + b1);
            float2 o1 = make_float2(acc[mf][nf][2] + b0, acc[mf][nf][3] + b1);
            *(float2*)(C + (size_t)row * N + col)       = o0;
            *(float2*)(C + (size_t)(row + 8) * N + col) = o1;
        }
    }
}

// ---------------------------------------------------------------------------
// K2: per-token rmsnorm(q), rmsnorm(k), RoPE, ReLU.
// Reads fp32 q,k from g_qkv; writes fp16 qf/kf into head-major g_qfh/g_kfh.
// ---------------------------------------------------------------------------
__global__ __launch_bounds__(256) void qk_prep_k(const float* __restrict__ gq,
                                                 const float* __restrict__ gk)
{
    const int t = blockIdx.x;
    const int b = t >> 12;
    const int l = t & (Lq - 1);
    const int tid = threadIdx.x;
    const float* row = g_qkv + (size_t)t * NQKV;
    float4 q = *(const float4*)(row + tid * 4);
    float4 k = *(const float4*)(row + Dq + tid * 4);
    float sq = q.x*q.x + q.y*q.y + q.z*q.z + q.w*q.w;
    float sk = k.x*k.x + k.y*k.y + k.z*k.z + k.w*k.w;
#pragma unroll
    for (int o = 16; o > 0; o >>= 1) {
        sq += __shfl_xor_sync(0xffffffffu, sq, o);
        sk += __shfl_xor_sync(0xffffffffu, sk, o);
    }
    __shared__ float wq[8], wk[8];
    __shared__ float bq, bk;
    const int warp = tid >> 5, lane = tid & 31;
    if (lane == 0) { wq[warp] = sq; wk[warp] = sk; }
    __syncthreads();
    if (tid == 0) {
        float aq = 0.0f, ak = 0.0f;
#pragma unroll
        for (int i = 0; i < 8; ++i) { aq += wq[i]; ak += wk[i]; }
        bq = rsqrtf(aq * (1.0f / 1024.0f) + RMSEPS);
        bk = rsqrtf(ak * (1.0f / 1024.0f) + RMSEPS);
    }
    __syncthreads();
    const float scq = bq, sck = bk;
    const int c0 = tid * 4;
    float qe[4] = {q.x, q.y, q.z, q.w};
    float ke[4] = {k.x, k.y, k.z, k.w};
#pragma unroll
    for (int i = 0; i < 4; ++i) {
        qe[i] *= scq * gq[c0 + i];
        ke[i] *= sck * gk[c0 + i];
    }
#pragma unroll
    for (int p = 0; p < 2; ++p) {
        int d = (c0 + 2 * p) & 63;
        int j = d >> 1;
        float c = g_cos[l * 32 + j];
        float s = g_sin[l * 32 + j];
        float q0 = qe[2*p], q1 = qe[2*p + 1];
        qe[2*p]     = q0 * c - q1 * s;
        qe[2*p + 1] = q0 * s + q1 * c;
        float k0 = ke[2*p], k1 = ke[2*p + 1];
        ke[2*p]     = k0 * c - k1 * s;
        ke[2*p + 1] = k0 * s + k1 * c;
    }
    const int h = c0 >> 6, d0 = c0 & 63;
    const size_t off = (((size_t)(b * Hq + h) * Lq) + l) * DHq + d0;
    uint2 qo, ko;
    *(__half2*)&qo.x = __floats2half2_rn(fmaxf(qe[0],0.f), fmaxf(qe[1],0.f));
    *(__half2*)&qo.y = __floats2half2_rn(fmaxf(qe[2],0.f), fmaxf(qe[3],0.f));
    *(__half2*)&ko.x = __floats2half2_rn(fmaxf(ke[0],0.f), fmaxf(ke[1],0.f));
    *(__half2*)&ko.y = __floats2half2_rn(fmaxf(ke[2],0.f), fmaxf(ke[3],0.f));
    *(uint2*)(g_qfh + off) = qo;
    *(uint2*)(g_kfh + off) = ko;
}

// ---------------------------------------------------------------------------
// K3: vk partials, register-tiled. CTA = (b*H+h, Lchunk of 512 tokens).
// kf from fp16 head-major buffer; v from fp32 g_qkv.
// ---------------------------------------------------------------------------
__global__ __launch_bounds__(256) void vk_accum_k() {
    const int bh = blockIdx.x;
    const int chunk = blockIdx.y;       // 0..NCHUNK-1
    const int b = bh >> 4, h = bh & 15;
    const int tid = threadIdx.x;
    __shared__ __align__(16) float kf_s[32 * 64];
    __shared__ __align__(16) float vp_s[32 * 64];
    const int pq = tid >> 4;
    const int dq = tid & 15;
    float acc[4][4];
    float den[4] = {0.f, 0.f, 0.f, 0.f};
#pragma unroll
    for (int i = 0; i < 4; ++i)
#pragma unroll
        for (int j = 0; j < 4; ++j) acc[i][j] = 0.0f;

    const int l0 = chunk * (Lq / NCHUNK);
    const int tok0 = b * Lq + l0;
    const int r0 = tid >> 4;
    const int c4 = (tid & 15) << 2;
    const int lr  = tid >> 3;           // 0..31
    const int lc8 = (tid & 7) << 3;     // 0..56
    for (int sub = 0; sub < (Lq / NCHUNK) / 32; ++sub) {
        // kf: fp16 head-major, contiguous
        {
            const __half* ks = g_kfh + ((size_t)bh * Lq + l0 + sub * 32 + lr) * DHq + lc8;
            uint4 raw = *(const uint4*)ks;
            float2 f0 = __half22float2(*(__half2*)&raw.x);
            float2 f1 = __half22float2(*(__half2*)&raw.y);
            float2 f2 = __half22float2(*(__half2*)&raw.z);
            float2 f3 = __half22float2(*(__half2*)&raw.w);
            *(float4*)&kf_s[lr * 64 + lc8]     = make_float4(f0.x, f0.y, f1.x, f1.y);
            *(float4*)&kf_s[lr * 64 + lc8 + 4] = make_float4(f2.x, f2.y, f3.x, f3.y);
        }
        // v: fp32 from g_qkv
#pragma unroll
        for (int half = 0; half < 2; ++half) {
            int r = r0 + half * 16;
            const float* src = g_qkv + (size_t)(tok0 + sub * 32 + r) * NQKV + 2 * Dq + h * DHq + c4;
            *(float4*)&vp_s[r * 64 + c4] = *(const float4*)src;
        }
        __syncthreads();
#pragma unroll 8
        for (int r = 0; r < 32; ++r) {
            float4 vp = *(const float4*)&vp_s[r * 64 + pq * 4];
            float4 kf = *(const float4*)&kf_s[r * 64 + dq * 4];
            const float kfe[4] = {kf.x, kf.y, kf.z, kf.w};
            const float vpe[4] = {vp.x, vp.y, vp.z, vp.w};
#pragma unroll
            for (int i = 0; i < 4; ++i)
#pragma unroll
                for (int j = 0; j < 4; ++j)
                    acc[i][j] = fmaf(vpe[i], kfe[j], acc[i][j]);
            if (pq == 0) {
#pragma unroll
                for (int j = 0; j < 4; ++j) den[j] += kfe[j];
            }
        }
        __syncthreads();
    }
    float* dst = g_vkp + (size_t)chunk * (64 * 65 * 64) + bh * (65 * 64);
#pragma unroll
    for (int i = 0; i < 4; ++i) {
        float4 o = make_float4(acc[i][0], acc[i][1], acc[i][2], acc[i][3]);
        *(float4*)(dst + (pq * 4 + i) * 64 + dq * 4) = o;
    }
    if (pq == 0)
        *(float4*)(dst + 64 * 64 + dq * 4) = make_float4(den[0], den[1], den[2], den[3]);
}

// K4: deterministic reduce of the NCHUNK partials.
__global__ void vk_reduce_k() {
    int i = blockIdx.x * 256 + threadIdx.x;
    if (i >= 64 * 65 * 64) return;
    float s = 0.0f;
#pragma unroll
    for (int c = 0; c < NCHUNK; ++c) s += g_vkp[(size_t)c * (64 * 65 * 64) + i];
    g_vk[i] = s;
}

// ---------------------------------------------------------------------------
// K5: res = vk . qf ; attn = res[:64]/(res[64]+eps) -> fp16 into g_ah.
// qf from fp16 head-major buffer.
// ---------------------------------------------------------------------------
#define VKP 68
__global__ __launch_bounds__(256) void attn_apply_k() {
    const int bh = blockIdx.x;
    const int lt = blockIdx.y;
    const int b = bh >> 4, h = bh & 15;
    const int tid = threadIdx.x;
    __shared__ __align__(16) float qf_s[64 * 64];
    __shared__ __align__(16) float vk_s[65 * VKP];
    __shared__ float den_s[64];
#pragma unroll
    for (int ei = 0; ei < 17; ++ei) {
        int e = tid + ei * 256;
        if (e < 65 * 64) vk_s[(e >> 6) * VKP + (e & 63)] = g_vk[bh * (65 * 64) + e];
    }
    {
        const int r = tid >> 2;            // 0..63
        const int c16 = (tid & 3) << 4;    // 0,16,32,48
        const __half* src = g_qfh + ((size_t)bh * Lq + lt * 64 + r) * DHq + c16;
#pragma unroll
        for (int half8 = 0; half8 < 2; ++half8) {
            uint4 raw = *(const uint4*)(src + half8 * 8);
            float2 f0 = __half22float2(*(__half2*)&raw.x);
            float2 f1 = __half22float2(*(__half2*)&raw.y);
            float2 f2 = __half22float2(*(__half2*)&raw.z);
            float2 f3 = __half22float2(*(__half2*)&raw.w);
            *(float4*)&qf_s[r * 64 + c16 + half8 * 8]     = make_float4(f0.x, f0.y, f1.x, f1.y);
            *(float4*)&qf_s[r * 64 + c16 + half8 * 8 + 4] = make_float4(f2.x, f2.y, f3.x, f3.y);
        }
    }
    __syncthreads();
    if (tid < 64) {
        float d = 0.0f;
#pragma unroll
        for (int kk = 0; kk < 64; ++kk) {
            int k = (kk + tid) & 63;
            d = fmaf(vk_s[64 * VKP + k], qf_s[tid * 64 + k], d);
        }
        den_s[tid] = d;
    }
    __syncthreads();
    const int dd  = tid & 63;
    const int grp = tid >> 6;
    __half* outp = g_ah + (size_t)(b * Lq + lt * 64) * Dq + h * DHq + dd;
#pragma unroll 1
    for (int gi = 0; gi < 4; ++gi) {
        const int tokb = grp * 16 + gi * 4;
        float a0 = 0.f, a1 = 0.f, a2 = 0.f, a3 = 0.f;
#pragma unroll
        for (int k4 = 0; k4 < 16; ++k4) {
            float4 v  = *(const float4*)&vk_s[dd * VKP + k4 * 4];
            float4 q0 = *(const float4*)&qf_s[(tokb + 0) * 64 + k4 * 4];
            float4 q1 = *(const float4*)&qf_s[(tokb + 1) * 64 + k4 * 4];
            float4 q2 = *(const float4*)&qf_s[(tokb + 2) * 64 + k4 * 4];
            float4 q3 = *(const float4*)&qf_s[(tokb + 3) * 64 + k4 * 4];
            a0 = fmaf(v.x, q0.x, a0); a0 = fmaf(v.y, q0.y, a0);
            a0 = fmaf(v.z, q0.z, a0); a0 = fmaf(v.w, q0.w, a0);
            a1 = fmaf(v.x, q1.x, a1); a1 = fmaf(v.y, q1.y, a1);
            a1 = fmaf(v.z, q1.z, a1); a1 = fmaf(v.w, q1.w, a1);
            a2 = fmaf(v.x, q2.x, a2); a2 = fmaf(v.y, q2.y, a2);
            a2 = fmaf(v.z, q2.z, a2); a2 = fmaf(v.w, q2.w, a2);
            a3 = fmaf(v.x, q3.x, a3); a3 = fmaf(v.y, q3.y, a3);
            a3 = fmaf(v.z, q3.z, a3); a3 = fmaf(v.w, q3.w, a3);
        }
        outp[(size_t)(tokb + 0) * Dq] = __float2half_rn(a0 / (den_s[tokb + 0] + EPSLIN));
        outp[(size_t)(tokb + 1) * Dq] = __float2half_rn(a1 / (den_s[tokb + 1] + EPSLIN));
        outp[(size_t)(tokb + 2) * Dq] = __float2half_rn(a2 / (den_s[tokb + 2] + EPSLIN));
        outp[(size_t)(tokb + 3) * Dq] = __float2half_rn(a3 / (den_s[tokb + 3] + EPSLIN));
    }
}

// ---------------------------------------------------------------------------
// K7: final rmsnorm over g_y rows -> d_out
// ---------------------------------------------------------------------------
__global__ __launch_bounds__(256) void out_rms_k(const float* __restrict__ gout,
                                                 float* __restrict__ out)
{
    const int t = blockIdx.x;
    const int tid = threadIdx.x;
    const float* row = g_y + (size_t)t * Dq;
    float4 y = *(const float4*)(row + tid * 4);
    float ss = y.x*y.x + y.y*y.y + y.z*y.z + y.w*y.w;
#pragma unroll
    for (int o = 16; o > 0; o >>= 1) ss += __shfl_xor_sync(0xffffffffu, ss, o);
    __shared__ float w[8];
    __shared__ float bsc;
    if ((tid & 31) == 0) w[tid >> 5] = ss;
    __syncthreads();
    if (tid == 0) {
        float a = 0.0f;
#pragma unroll
        for (int i = 0; i < 8; ++i) a += w[i];
        bsc = rsqrtf(a * (1.0f / 1024.0f) + RMSEPS);
    }
    __syncthreads();
    const float sc = bsc;
    const int c0 = tid * 4;
    float4 o4;
    o4.x = y.x * sc * gout[c0 + 0];
    o4.y = y.y * sc * gout[c0 + 1];
    o4.z = y.z * sc * gout[c0 + 2];
    o4.w = y.w * sc * gout[c0 + 3];
    *(float4*)(out + (size_t)t * Dq + c0) = o4;
}

// ---------------------------------------------------------------------------
extern "C" void kernel_launch(void* const* d_in, const int* in_sizes, int n_in,
                              void* d_out, int out_size) {
    (void)in_sizes; (void)n_in; (void)out_size;
    const float* x    = (const float*)d_in[0];
    const float* Wqkv = (const float*)d_in[1];
    const float* bqkv = (const float*)d_in[2];
    const float* gq   = (const float*)d_in[3];
    const float* gk   = (const float*)d_in[4];
    const float* Wout = (const float*)d_in[5];
    const float* bout = (const float*)d_in[6];
    const float* gout = (const float*)d_in[7];
    float* out = (float*)d_out;

    float *qkv_p, *y_p;
    __half *xh, *ah, *wh1, *wh2;
    cudaGetSymbolAddress((void**)&qkv_p, g_qkv);
    cudaGetSymbolAddress((void**)&y_p,   g_y);
    cudaGetSymbolAddress((void**)&xh,  g_xh);
    cudaGetSymbolAddress((void**)&ah,  g_ah);
    cudaGetSymbolAddress((void**)&wh1, g_wh1);
    cudaGetSymbolAddress((void**)&wh2, g_wh2);

    const int DSMEM = NSTG * STAGE;   // 81920
    cudaFuncSetAttribute(gemm_hmma3_k, cudaFuncAttributeMaxDynamicSharedMemorySize, DSMEM);

    rope_tables_k<<<(Lq * 32 + 255) / 256, 256>>>();                          // 0
    to_half_k<<<(MTOK * Dq / 4 + 255) / 256, 256>>>(x, xh, MTOK * Dq / 4);    // 1
    to_half_k<<<(NQKV * Dq / 4 + 255) / 256, 256>>>(Wqkv, wh1, NQKV * Dq / 4);// 2
    gemm_hmma3_k<<<dim3(NQKV / 128, MTOK / 128), 256, DSMEM>>>(               // 3 (profiled slot)
        xh, wh1, bqkv, qkv_p, NQKV);
    to_half_k<<<(Dq * Dq / 4 + 255) / 256, 256>>>(Wout, wh2, Dq * Dq / 4);    // 4
    qk_prep_k<<<MTOK, 256>>>(gq, gk);
    vk_accum_k<<<dim3(64, NCHUNK), 256>>>();
    vk_reduce_k<<<(64 * 65 * 64 + 255) / 256, 256>>>();
    attn_apply_k<<<dim3(64, 64), 256>>>();
    gemm_hmma3_k<<<dim3(Dq / 128, MTOK / 128), 256, DSMEM>>>(
        ah, wh2, bout, y_p, Dq);
    out_rms_k<<<MTOK, 256>>>(gout, out);
}

// round 12
// speedup vs baseline: 1.5576x; 1.0304x over previous
#include <cuda_runtime.h>
#include <cuda_fp16.h>
#include <math.h>
#include <stdint.h>

// Problem constants
#define Bq    4
#define Lq    4096
#define Dq    1024
#define Hq    16
#define DHq   64
#define MTOK  (Bq*Lq)      // 16384
#define NQKV  (3*Dq)       // 3072
#define RMSEPS 1.1920929e-07f
#define EPSLIN 1e-06f
#define NCHUNK 8

// Scratch (device globals — no allocation allowed)
__device__ __align__(256) float g_qkv [(size_t)MTOK * NQKV];   // fp32 qkv (v read later)
__device__ __align__(256) float g_vkp [NCHUNK * 64 * 65 * DHq];
__device__ __align__(256) float g_vk  [64 * 65 * DHq];
__device__ __align__(256) float g_y   [(size_t)MTOK * Dq];
__device__ __align__(256) float g_cos [Lq * 32];
__device__ __align__(256) float g_sin [Lq * 32];
// fp16 operands / intermediates
__device__ __align__(256) __half g_xh [(size_t)MTOK * Dq];
__device__ __align__(256) __half g_ah [(size_t)MTOK * Dq];    // attn in fp16 (gemm2 A)
__device__ __align__(256) __half g_wh1[(size_t)NQKV * Dq];
__device__ __align__(256) __half g_wh2[(size_t)Dq * Dq];
__device__ __align__(256) __half g_qfh[(size_t)MTOK * Dq];    // qf, head-major [bh][l][64]
__device__ __align__(256) __half g_kfh[(size_t)MTOK * Dq];    // kf, head-major [bh][l][64]

// ---------------------------------------------------------------------------
__device__ __forceinline__ uint32_t smem_u32(const void* p) {
    uint32_t a;
    asm("{ .reg .u64 t; cvta.to.shared.u64 t, %1; cvt.u32.u64 %0, t; }" : "=r"(a) : "l"(p));
    return a;
}
__device__ __forceinline__ void cp_async16(uint32_t dst, const void* src) {
    asm volatile("cp.async.cg.shared.global [%0], [%1], 16;" :: "r"(dst), "l"(src));
}
#define CP_COMMIT() asm volatile("cp.async.commit_group;" ::: "memory")
template <int N>
__device__ __forceinline__ void cp_wait() {
    asm volatile("cp.async.wait_group %0;" :: "n"(N) : "memory");
}
__device__ __forceinline__ void ldm_x4(uint32_t* r, uint32_t addr) {
    asm volatile("ldmatrix.sync.aligned.m8n8.x4.shared.b16 {%0,%1,%2,%3}, [%4];"
                 : "=r"(r[0]), "=r"(r[1]), "=r"(r[2]), "=r"(r[3]) : "r"(addr));
}
__device__ __forceinline__ void mma_f16(float* c, const uint32_t* a, const uint32_t* b) {
    asm volatile(
        "mma.sync.aligned.m16n8k16.row.col.f32.f16.f16.f32 "
        "{%0,%1,%2,%3}, {%4,%5,%6,%7}, {%8,%9}, {%0,%1,%2,%3};"
        : "+f"(c[0]), "+f"(c[1]), "+f"(c[2]), "+f"(c[3])
        : "r"(a[0]), "r"(a[1]), "r"(a[2]), "r"(a[3]), "r"(b[0]), "r"(b[1]));
}

// ---------------------------------------------------------------------------
// K0: fused prep — rope tables + three fp32->fp16 conversions, grid-partitioned.
// ---------------------------------------------------------------------------
__device__ __forceinline__ void conv4(const float* __restrict__ s,
                                      __half* __restrict__ d, int i) {
    float4 v = ((const float4*)s)[i];
    ((__half2*)d)[2*i]   = __floats2half2_rn(v.x, v.y);
    ((__half2*)d)[2*i+1] = __floats2half2_rn(v.z, v.w);
}
#define NB_ROPE 512
#define NB_X    16384
#define NB_W1   3072
#define NB_W2   1024
__global__ __launch_bounds__(256) void prep_fused_k(
    const float* __restrict__ x, const float* __restrict__ W1,
    const float* __restrict__ W2,
    __half* __restrict__ xh, __half* __restrict__ wh1, __half* __restrict__ wh2)
{
    const int bid = blockIdx.x;
    const int tid = threadIdx.x;
    if (bid < NB_ROPE) {
        int idx = bid * 256 + tid;
        int l = idx >> 5, j = idx & 31;
        float inv_freq = expf(-(float)j * (9.210340371976184f / 32.0f));
        float ang = (float)l * inv_freq;
        g_cos[idx] = cosf(ang);
        g_sin[idx] = sinf(ang);
    } else if (bid < NB_ROPE + NB_X) {
        conv4(x, xh, (bid - NB_ROPE) * 256 + tid);
    } else if (bid < NB_ROPE + NB_X + NB_W1) {
        conv4(W1, wh1, (bid - NB_ROPE - NB_X) * 256 + tid);
    } else {
        conv4(W2, wh2, (bid - NB_ROPE - NB_X - NB_W1) * 256 + tid);
    }
}

// ---------------------------------------------------------------------------
// HMMA GEMM (R9-frozen): C[m,n] = sum_k A[m,k]*B[n,k] + bias[n], K = 1024.
// ---------------------------------------------------------------------------
#define BKS     32
#define NSLAB   32
#define PITCH   80
#define TILEB   (128 * PITCH)
#define OFF_B   TILEB
#define STAGE   (2 * TILEB)
#define NSTG    4

__global__ __launch_bounds__(256, 2)
void gemm_hmma3_k(const __half* __restrict__ A, const __half* __restrict__ B,
                  const float* __restrict__ bias, float* __restrict__ C, int N)
{
    extern __shared__ __align__(16) char sm[];
    const uint32_t smb = smem_u32(sm);
    const int tid  = threadIdx.x;
    const int wid  = tid >> 5, lane = tid & 31;
    const int wm   = wid & 3, wn = wid >> 2;
    const int g    = lane >> 2, t = lane & 3;
    const int m0   = blockIdx.y * 128;
    const int n0   = blockIdx.x * 128;

    float acc[2][8][4];
#pragma unroll
    for (int mf = 0; mf < 2; ++mf)
#pragma unroll
        for (int nf = 0; nf < 8; ++nf)
#pragma unroll
            for (int e = 0; e < 4; ++e) acc[mf][nf][e] = 0.0f;

    const int crow = tid >> 2;
    const int c16  = tid & 3;
    auto load_slab = [&](int ks, int st) {
        uint32_t base = smb + st * STAGE;
#pragma unroll
        for (int j = 0; j < 2; ++j) {
            int row = crow + j * 64;
            uint32_t d = base + row * PITCH + c16 * 16;
            cp_async16(d,         A + (size_t)(m0 + row) * 1024 + ks * BKS + c16 * 8);
            cp_async16(d + OFF_B, B + (size_t)(n0 + row) * 1024 + ks * BKS + c16 * 8);
        }
        CP_COMMIT();
    };

    const int quad = lane >> 3, r8 = lane & 7;
    const uint32_t aoff = (uint32_t)((wm * 32 + (quad & 1) * 8 + r8) * PITCH + (quad >> 1) * 16);
    const uint32_t boff = (uint32_t)((wn * 64 + (quad >> 1) * 8 + r8) * PITCH + (quad & 1) * 16);

    load_slab(0, 0);
    load_slab(1, 1);
    load_slab(2, 2);

#pragma unroll 1
    for (int i = 0; i < NSLAB; ++i) {
        cp_wait<2>();
        __syncthreads();
        if (i + 3 < NSLAB) load_slab(i + 3, (i + 3) & 3);
        else CP_COMMIT();
        const uint32_t st = smb + (uint32_t)(i & 3) * STAGE;
#pragma unroll
        for (int kk = 0; kk < 2; ++kk) {
            uint32_t a[2][4];
            ldm_x4(a[0], st + aoff + kk * 32);
            ldm_x4(a[1], st + aoff + kk * 32 + 16 * PITCH);
            const uint32_t bb = st + OFF_B + boff + kk * 32;
#pragma unroll
            for (int nf2 = 0; nf2 < 4; ++nf2) {
                uint32_t b[4];
                ldm_x4(b, bb + nf2 * (16 * PITCH));
                mma_f16(acc[0][2*nf2],   a[0], b);
                mma_f16(acc[0][2*nf2+1], a[0], b + 2);
                mma_f16(acc[1][2*nf2],   a[1], b);
                mma_f16(acc[1][2*nf2+1], a[1], b + 2);
            }
        }
    }

#pragma unroll
    for (int mf = 0; mf < 2; ++mf) {
        int row = m0 + wm * 32 + mf * 16 + g;
#pragma unroll
        for (int nf = 0; nf < 8; ++nf) {
            int col = n0 + wn * 64 + nf * 8 + 2 * t;
            float b0 = bias[col], b1 = bias[col + 1];
            float2 o0 = make_float2(acc[mf][nf][0] + b0, acc[mf][nf][1] + b1);
            float2 o1 = make_float2(acc[mf][nf][2] + b0, acc[mf][nf][3] + b1);
            *(float2*)(C + (size_t)row * N + col)       = o0;
            *(float2*)(C + (size_t)(row + 8) * N + col) = o1;
        }
    }
}

// ---------------------------------------------------------------------------
// K2: qk_prep, warp-per-token (no block barriers). Reads fp32 q,k from g_qkv;
// writes fp16 qf/kf head-major.
// ---------------------------------------------------------------------------
__global__ __launch_bounds__(256) void qk_prep_k(const float* __restrict__ gq,
                                                 const float* __restrict__ gk)
{
    const int warp = threadIdx.x >> 5, lane = threadIdx.x & 31;
    const int t = blockIdx.x * 8 + warp;
    const int b = t >> 12;
    const int l = t & (Lq - 1);
    const float* row = g_qkv + (size_t)t * NQKV;
    float4 qv[8], kv[8];
    float sq = 0.0f, sk = 0.0f;
#pragma unroll
    for (int s = 0; s < 8; ++s) {
        qv[s] = *(const float4*)(row + lane * 4 + s * 128);
        kv[s] = *(const float4*)(row + Dq + lane * 4 + s * 128);
        sq += qv[s].x*qv[s].x + qv[s].y*qv[s].y + qv[s].z*qv[s].z + qv[s].w*qv[s].w;
        sk += kv[s].x*kv[s].x + kv[s].y*kv[s].y + kv[s].z*kv[s].z + kv[s].w*kv[s].w;
    }
#pragma unroll
    for (int o = 16; o > 0; o >>= 1) {
        sq += __shfl_xor_sync(0xffffffffu, sq, o);
        sk += __shfl_xor_sync(0xffffffffu, sk, o);
    }
    const float scq = rsqrtf(sq * (1.0f / 1024.0f) + RMSEPS);
    const float sck = rsqrtf(sk * (1.0f / 1024.0f) + RMSEPS);
#pragma unroll
    for (int s = 0; s < 8; ++s) {
        const int c0 = lane * 4 + s * 128;
        float4 gq4 = *(const float4*)(gq + c0);
        float4 gk4 = *(const float4*)(gk + c0);
        float qe[4] = {qv[s].x*scq*gq4.x, qv[s].y*scq*gq4.y, qv[s].z*scq*gq4.z, qv[s].w*scq*gq4.w};
        float ke[4] = {kv[s].x*sck*gk4.x, kv[s].y*sck*gk4.y, kv[s].z*sck*gk4.z, kv[s].w*sck*gk4.w};
#pragma unroll
        for (int p = 0; p < 2; ++p) {
            int d = (c0 + 2 * p) & 63;
            int j = d >> 1;
            float c = g_cos[l * 32 + j];
            float sn = g_sin[l * 32 + j];
            float q0 = qe[2*p], q1 = qe[2*p + 1];
            qe[2*p]     = q0 * c - q1 * sn;
            qe[2*p + 1] = q0 * sn + q1 * c;
            float k0 = ke[2*p], k1 = ke[2*p + 1];
            ke[2*p]     = k0 * c - k1 * sn;
            ke[2*p + 1] = k0 * sn + k1 * c;
        }
        const int h = c0 >> 6, d0 = c0 & 63;
        const size_t off = (((size_t)(b * Hq + h) * Lq) + l) * DHq + d0;
        uint2 qo, ko;
        *(__half2*)&qo.x = __floats2half2_rn(fmaxf(qe[0],0.f), fmaxf(qe[1],0.f));
        *(__half2*)&qo.y = __floats2half2_rn(fmaxf(qe[2],0.f), fmaxf(qe[3],0.f));
        *(__half2*)&ko.x = __floats2half2_rn(fmaxf(ke[0],0.f), fmaxf(ke[1],0.f));
        *(__half2*)&ko.y = __floats2half2_rn(fmaxf(ke[2],0.f), fmaxf(ke[3],0.f));
        *(uint2*)(g_qfh + off) = qo;
        *(uint2*)(g_kfh + off) = ko;
    }
}

// ---------------------------------------------------------------------------
// K3: vk partials, register-staged pipeline. CTA = (bh, Lchunk of 512 tokens).
// ---------------------------------------------------------------------------
__global__ __launch_bounds__(256) void vk_accum_k() {
    const int bh = blockIdx.x;
    const int chunk = blockIdx.y;
    const int b = bh >> 4, h = bh & 15;
    const int tid = threadIdx.x;
    __shared__ __align__(16) float kf_s[32 * 64];
    __shared__ __align__(16) float vp_s[32 * 64];
    const int pq = tid >> 4;
    const int dq = tid & 15;
    float acc[4][4];
    float den[4] = {0.f, 0.f, 0.f, 0.f};
#pragma unroll
    for (int i = 0; i < 4; ++i)
#pragma unroll
        for (int j = 0; j < 4; ++j) acc[i][j] = 0.0f;

    const int l0 = chunk * (Lq / NCHUNK);
    const int tok0 = b * Lq + l0;
    const int r0 = tid >> 4;
    const int c4 = (tid & 15) << 2;
    const int lr  = tid >> 3;
    const int lc8 = (tid & 7) << 3;

    uint4 kraw;
    float4 vst0, vst1;
    auto ldg_sub = [&](int sub) {
        kraw = *(const uint4*)(g_kfh + ((size_t)bh * Lq + l0 + sub * 32 + lr) * DHq + lc8);
        vst0 = *(const float4*)(g_qkv + (size_t)(tok0 + sub * 32 + r0) * NQKV + 2 * Dq + h * DHq + c4);
        vst1 = *(const float4*)(g_qkv + (size_t)(tok0 + sub * 32 + r0 + 16) * NQKV + 2 * Dq + h * DHq + c4);
    };
    ldg_sub(0);

    const int NSUB = (Lq / NCHUNK) / 32;
#pragma unroll 1
    for (int sub = 0; sub < NSUB; ++sub) {
        {
            float2 f0 = __half22float2(*(__half2*)&kraw.x);
            float2 f1 = __half22float2(*(__half2*)&kraw.y);
            float2 f2 = __half22float2(*(__half2*)&kraw.z);
            float2 f3 = __half22float2(*(__half2*)&kraw.w);
            *(float4*)&kf_s[lr * 64 + lc8]     = make_float4(f0.x, f0.y, f1.x, f1.y);
            *(float4*)&kf_s[lr * 64 + lc8 + 4] = make_float4(f2.x, f2.y, f3.x, f3.y);
            *(float4*)&vp_s[r0 * 64 + c4]        = vst0;
            *(float4*)&vp_s[(r0 + 16) * 64 + c4] = vst1;
        }
        __syncthreads();
        if (sub + 1 < NSUB) ldg_sub(sub + 1);   // overlap with compute below
#pragma unroll 8
        for (int r = 0; r < 32; ++r) {
            float4 vp = *(const float4*)&vp_s[r * 64 + pq * 4];
            float4 kf = *(const float4*)&kf_s[r * 64 + dq * 4];
            const float kfe[4] = {kf.x, kf.y, kf.z, kf.w};
            const float vpe[4] = {vp.x, vp.y, vp.z, vp.w};
#pragma unroll
            for (int i = 0; i < 4; ++i)
#pragma unroll
                for (int j = 0; j < 4; ++j)
                    acc[i][j] = fmaf(vpe[i], kfe[j], acc[i][j]);
            if (pq == 0) {
#pragma unroll
                for (int j = 0; j < 4; ++j) den[j] += kfe[j];
            }
        }
        __syncthreads();
    }
    float* dst = g_vkp + (size_t)chunk * (64 * 65 * 64) + bh * (65 * 64);
#pragma unroll
    for (int i = 0; i < 4; ++i) {
        float4 o = make_float4(acc[i][0], acc[i][1], acc[i][2], acc[i][3]);
        *(float4*)(dst + (pq * 4 + i) * 64 + dq * 4) = o;
    }
    if (pq == 0)
        *(float4*)(dst + 64 * 64 + dq * 4) = make_float4(den[0], den[1], den[2], den[3]);
}

// K4: deterministic reduce of the NCHUNK partials.
__global__ void vk_reduce_k() {
    int i = blockIdx.x * 256 + threadIdx.x;
    if (i >= 64 * 65 * 64) return;
    float s = 0.0f;
#pragma unroll
    for (int c = 0; c < NCHUNK; ++c) s += g_vkp[(size_t)c * (64 * 65 * 64) + i];
    g_vk[i] = s;
}

// ---------------------------------------------------------------------------
// K5: res = vk . qf ; attn = res[:64]/(res[64]+eps) -> fp16 into g_ah.
// ---------------------------------------------------------------------------
#define VKP 68
__global__ __launch_bounds__(256) void attn_apply_k() {
    const int bh = blockIdx.x;
    const int lt = blockIdx.y;
    const int b = bh >> 4, h = bh & 15;
    const int tid = threadIdx.x;
    __shared__ __align__(16) float qf_s[64 * 64];
    __shared__ __align__(16) float vk_s[65 * VKP];
    __shared__ float den_s[64];
#pragma unroll
    for (int ei = 0; ei < 17; ++ei) {
        int e = tid + ei * 256;
        if (e < 65 * 64) vk_s[(e >> 6) * VKP + (e & 63)] = g_vk[bh * (65 * 64) + e];
    }
    {
        const int r = tid >> 2;
        const int c16 = (tid & 3) << 4;
        const __half* src = g_qfh + ((size_t)bh * Lq + lt * 64 + r) * DHq + c16;
#pragma unroll
        for (int half8 = 0; half8 < 2; ++half8) {
            uint4 raw = *(const uint4*)(src + half8 * 8);
            float2 f0 = __half22float2(*(__half2*)&raw.x);
            float2 f1 = __half22float2(*(__half2*)&raw.y);
            float2 f2 = __half22float2(*(__half2*)&raw.z);
            float2 f3 = __half22float2(*(__half2*)&raw.w);
            *(float4*)&qf_s[r * 64 + c16 + half8 * 8]     = make_float4(f0.x, f0.y, f1.x, f1.y);
            *(float4*)&qf_s[r * 64 + c16 + half8 * 8 + 4] = make_float4(f2.x, f2.y, f3.x, f3.y);
        }
    }
    __syncthreads();
    if (tid < 64) {
        float d = 0.0f;
#pragma unroll
        for (int kk = 0; kk < 64; ++kk) {
            int k = (kk + tid) & 63;
            d = fmaf(vk_s[64 * VKP + k], qf_s[tid * 64 + k], d);
        }
        den_s[tid] = d;
    }
    __syncthreads();
    const int dd  = tid & 63;
    const int grp = tid >> 6;
    __half* outp = g_ah + (size_t)(b * Lq + lt * 64) * Dq + h * DHq + dd;
#pragma unroll 1
    for (int gi = 0; gi < 4; ++gi) {
        const int tokb = grp * 16 + gi * 4;
        float a0 = 0.f, a1 = 0.f, a2 = 0.f, a3 = 0.f;
#pragma unroll
        for (int k4 = 0; k4 < 16; ++k4) {
            float4 v  = *(const float4*)&vk_s[dd * VKP + k4 * 4];
            float4 q0 = *(const float4*)&qf_s[(tokb + 0) * 64 + k4 * 4];
            float4 q1 = *(const float4*)&qf_s[(tokb + 1) * 64 + k4 * 4];
            float4 q2 = *(const float4*)&qf_s[(tokb + 2) * 64 + k4 * 4];
            float4 q3 = *(const float4*)&qf_s[(tokb + 3) * 64 + k4 * 4];
            a0 = fmaf(v.x, q0.x, a0); a0 = fmaf(v.y, q0.y, a0);
            a0 = fmaf(v.z, q0.z, a0); a0 = fmaf(v.w, q0.w, a0);
            a1 = fmaf(v.x, q1.x, a1); a1 = fmaf(v.y, q1.y, a1);
            a1 = fmaf(v.z, q1.z, a1); a1 = fmaf(v.w, q1.w, a1);
            a2 = fmaf(v.x, q2.x, a2); a2 = fmaf(v.y, q2.y, a2);
            a2 = fmaf(v.z, q2.z, a2); a2 = fmaf(v.w, q2.w, a2);
            a3 = fmaf(v.x, q3.x, a3); a3 = fmaf(v.y, q3.y, a3);
            a3 = fmaf(v.z, q3.z, a3); a3 = fmaf(v.w, q3.w, a3);
        }
        outp[(size_t)(tokb + 0) * Dq] = __float2half_rn(a0 / (den_s[tokb + 0] + EPSLIN));
        outp[(size_t)(tokb + 1) * Dq] = __float2half_rn(a1 / (den_s[tokb + 1] + EPSLIN));
        outp[(size_t)(tokb + 2) * Dq] = __float2half_rn(a2 / (den_s[tokb + 2] + EPSLIN));
        outp[(size_t)(tokb + 3) * Dq] = __float2half_rn(a3 / (den_s[tokb + 3] + EPSLIN));
    }
}

// ---------------------------------------------------------------------------
// K7: final rmsnorm, warp-per-token (no block barriers).
// ---------------------------------------------------------------------------
__global__ __launch_bounds__(256) void out_rms_k(const float* __restrict__ gout,
                                                 float* __restrict__ out)
{
    const int warp = threadIdx.x >> 5, lane = threadIdx.x & 31;
    const int t = blockIdx.x * 8 + warp;
    const float* row = g_y + (size_t)t * Dq;
    float4 y[8];
    float ss = 0.0f;
#pragma unroll
    for (int s = 0; s < 8; ++s) {
        y[s] = *(const float4*)(row + lane * 4 + s * 128);
        ss += y[s].x*y[s].x + y[s].y*y[s].y + y[s].z*y[s].z + y[s].w*y[s].w;
    }
#pragma unroll
    for (int o = 16; o > 0; o >>= 1) ss += __shfl_xor_sync(0xffffffffu, ss, o);
    const float sc = rsqrtf(ss * (1.0f / 1024.0f) + RMSEPS);
#pragma unroll
    for (int s = 0; s < 8; ++s) {
        const int c0 = lane * 4 + s * 128;
        float4 gg = *(const float4*)(gout + c0);
        float4 o4;
        o4.x = y[s].x * sc * gg.x;
        o4.y = y[s].y * sc * gg.y;
        o4.z = y[s].z * sc * gg.z;
        o4.w = y[s].w * sc * gg.w;
        *(float4*)(out + (size_t)t * Dq + c0) = o4;
    }
}

// ---------------------------------------------------------------------------
extern "C" void kernel_launch(void* const* d_in, const int* in_sizes, int n_in,
                              void* d_out, int out_size) {
    (void)in_sizes; (void)n_in; (void)out_size;
    const float* x    = (const float*)d_in[0];
    const float* Wqkv = (const float*)d_in[1];
    const float* bqkv = (const float*)d_in[2];
    const float* gq   = (const float*)d_in[3];
    const float* gk   = (const float*)d_in[4];
    const float* Wout = (const float*)d_in[5];
    const float* bout = (const float*)d_in[6];
    const float* gout = (const float*)d_in[7];
    float* out = (float*)d_out;

    float *qkv_p, *y_p;
    __half *xh, *ah, *wh1, *wh2;
    cudaGetSymbolAddress((void**)&qkv_p, g_qkv);
    cudaGetSymbolAddress((void**)&y_p,   g_y);
    cudaGetSymbolAddress((void**)&xh,  g_xh);
    cudaGetSymbolAddress((void**)&ah,  g_ah);
    cudaGetSymbolAddress((void**)&wh1, g_wh1);
    cudaGetSymbolAddress((void**)&wh2, g_wh2);

    const int DSMEM = NSTG * STAGE;   // 81920
    cudaFuncSetAttribute(gemm_hmma3_k, cudaFuncAttributeMaxDynamicSharedMemorySize, DSMEM);

    prep_fused_k<<<NB_ROPE + NB_X + NB_W1 + NB_W2, 256>>>(x, Wqkv, Wout, xh, wh1, wh2); // 0
    gemm_hmma3_k<<<dim3(NQKV / 128, MTOK / 128), 256, DSMEM>>>(                          // 1
        xh, wh1, bqkv, qkv_p, NQKV);
    qk_prep_k<<<MTOK / 8, 256>>>(gq, gk);                                                // 2
    vk_accum_k<<<dim3(64, NCHUNK), 256>>>();                                             // 3 (profiled)
    vk_reduce_k<<<(64 * 65 * 64 + 255) / 256, 256>>>();
    attn_apply_k<<<dim3(64, 64), 256>>>();
    gemm_hmma3_k<<<dim3(Dq / 128, MTOK / 128), 256, DSMEM>>>(
        ah, wh2, bout, y_p, Dq);
    out_rms_k<<<MTOK / 8, 256>>>(gout, out);
}

// round 13
// speedup vs baseline: 1.7572x; 1.1281x over previous
#include <cuda_runtime.h>
#include <cuda_fp16.h>
#include <math.h>
#include <stdint.h>

// Problem constants
#define Bq    4
#define Lq    4096
#define Dq    1024
#define Hq    16
#define DHq   64
#define MTOK  (Bq*Lq)      // 16384
#define NQKV  (3*Dq)       // 3072
#define RMSEPS 1.1920929e-07f
#define EPSLIN 1e-06f
#define NCHUNK 16

// Scratch (device globals — no allocation allowed)
__device__ __align__(256) float g_qkv [(size_t)MTOK * NQKV];   // fp32 qkv (v read later)
__device__ __align__(256) float g_vkp [NCHUNK * 64 * 65 * DHq];
__device__ __align__(256) float g_vkden[64 * DHq];             // den row (p=64), fp32
__device__ __align__(256) float g_y   [(size_t)MTOK * Dq];
__device__ __align__(256) float g_cos [Lq * 32];
__device__ __align__(256) float g_sin [Lq * 32];
// fp16 operands / intermediates
__device__ __align__(256) __half g_xh [(size_t)MTOK * Dq];
__device__ __align__(256) __half g_ah [(size_t)MTOK * Dq];    // attn in fp16 (gemm2 A)
__device__ __align__(256) __half g_wh1[(size_t)NQKV * Dq];
__device__ __align__(256) __half g_wh2[(size_t)Dq * Dq];
__device__ __align__(256) __half g_qfh[(size_t)MTOK * Dq];    // qf, head-major [bh][l][64]
__device__ __align__(256) __half g_kfh[(size_t)MTOK * Dq];    // kf, head-major [bh][l][64]
__device__ __align__(256) __half g_vkh[64 * 64 * DHq];        // vk rows 0..63, fp16 [bh][p][d]

// ---------------------------------------------------------------------------
__device__ __forceinline__ uint32_t smem_u32(const void* p) {
    uint32_t a;
    asm("{ .reg .u64 t; cvta.to.shared.u64 t, %1; cvt.u32.u64 %0, t; }" : "=r"(a) : "l"(p));
    return a;
}
__device__ __forceinline__ void cp_async16(uint32_t dst, const void* src) {
    asm volatile("cp.async.cg.shared.global [%0], [%1], 16;" :: "r"(dst), "l"(src));
}
#define CP_COMMIT() asm volatile("cp.async.commit_group;" ::: "memory")
template <int N>
__device__ __forceinline__ void cp_wait() {
    asm volatile("cp.async.wait_group %0;" :: "n"(N) : "memory");
}
__device__ __forceinline__ void ldm_x4(uint32_t* r, uint32_t addr) {
    asm volatile("ldmatrix.sync.aligned.m8n8.x4.shared.b16 {%0,%1,%2,%3}, [%4];"
                 : "=r"(r[0]), "=r"(r[1]), "=r"(r[2]), "=r"(r[3]) : "r"(addr));
}
__device__ __forceinline__ void mma_f16(float* c, const uint32_t* a, const uint32_t* b) {
    asm volatile(
        "mma.sync.aligned.m16n8k16.row.col.f32.f16.f16.f32 "
        "{%0,%1,%2,%3}, {%4,%5,%6,%7}, {%8,%9}, {%0,%1,%2,%3};"
        : "+f"(c[0]), "+f"(c[1]), "+f"(c[2]), "+f"(c[3])
        : "r"(a[0]), "r"(a[1]), "r"(a[2]), "r"(a[3]), "r"(b[0]), "r"(b[1]));
}

// ---------------------------------------------------------------------------
// K0: fused prep — rope tables + three fp32->fp16 conversions, grid-partitioned.
// ---------------------------------------------------------------------------
__device__ __forceinline__ void conv4(const float* __restrict__ s,
                                      __half* __restrict__ d, int i) {
    float4 v = ((const float4*)s)[i];
    ((__half2*)d)[2*i]   = __floats2half2_rn(v.x, v.y);
    ((__half2*)d)[2*i+1] = __floats2half2_rn(v.z, v.w);
}
#define NB_ROPE 512
#define NB_X    16384
#define NB_W1   3072
#define NB_W2   1024
__global__ __launch_bounds__(256) void prep_fused_k(
    const float* __restrict__ x, const float* __restrict__ W1,
    const float* __restrict__ W2,
    __half* __restrict__ xh, __half* __restrict__ wh1, __half* __restrict__ wh2)
{
    const int bid = blockIdx.x;
    const int tid = threadIdx.x;
    if (bid < NB_ROPE) {
        int idx = bid * 256 + tid;
        int l = idx >> 5, j = idx & 31;
        float inv_freq = expf(-(float)j * (9.210340371976184f / 32.0f));
        float ang = (float)l * inv_freq;
        g_cos[idx] = cosf(ang);
        g_sin[idx] = sinf(ang);
    } else if (bid < NB_ROPE + NB_X) {
        conv4(x, xh, (bid - NB_ROPE) * 256 + tid);
    } else if (bid < NB_ROPE + NB_X + NB_W1) {
        conv4(W1, wh1, (bid - NB_ROPE - NB_X) * 256 + tid);
    } else {
        conv4(W2, wh2, (bid - NB_ROPE - NB_X - NB_W1) * 256 + tid);
    }
}

// ---------------------------------------------------------------------------
// HMMA GEMM (R9-frozen): C[m,n] = sum_k A[m,k]*B[n,k] + bias[n], K = 1024.
// ---------------------------------------------------------------------------
#define BKS     32
#define NSLAB   32
#define PITCH   80
#define TILEB   (128 * PITCH)
#define OFF_B   TILEB
#define STAGE   (2 * TILEB)
#define NSTG    4

__global__ __launch_bounds__(256, 2)
void gemm_hmma3_k(const __half* __restrict__ A, const __half* __restrict__ B,
                  const float* __restrict__ bias, float* __restrict__ C, int N)
{
    extern __shared__ __align__(16) char sm[];
    const uint32_t smb = smem_u32(sm);
    const int tid  = threadIdx.x;
    const int wid  = tid >> 5, lane = tid & 31;
    const int wm   = wid & 3, wn = wid >> 2;
    const int g    = lane >> 2, t = lane & 3;
    const int m0   = blockIdx.y * 128;
    const int n0   = blockIdx.x * 128;

    float acc[2][8][4];
#pragma unroll
    for (int mf = 0; mf < 2; ++mf)
#pragma unroll
        for (int nf = 0; nf < 8; ++nf)
#pragma unroll
            for (int e = 0; e < 4; ++e) acc[mf][nf][e] = 0.0f;

    const int crow = tid >> 2;
    const int c16  = tid & 3;
    auto load_slab = [&](int ks, int st) {
        uint32_t base = smb + st * STAGE;
#pragma unroll
        for (int j = 0; j < 2; ++j) {
            int row = crow + j * 64;
            uint32_t d = base + row * PITCH + c16 * 16;
            cp_async16(d,         A + (size_t)(m0 + row) * 1024 + ks * BKS + c16 * 8);
            cp_async16(d + OFF_B, B + (size_t)(n0 + row) * 1024 + ks * BKS + c16 * 8);
        }
        CP_COMMIT();
    };

    const int quad = lane >> 3, r8 = lane & 7;
    const uint32_t aoff = (uint32_t)((wm * 32 + (quad & 1) * 8 + r8) * PITCH + (quad >> 1) * 16);
    const uint32_t boff = (uint32_t)((wn * 64 + (quad >> 1) * 8 + r8) * PITCH + (quad & 1) * 16);

    load_slab(0, 0);
    load_slab(1, 1);
    load_slab(2, 2);

#pragma unroll 1
    for (int i = 0; i < NSLAB; ++i) {
        cp_wait<2>();
        __syncthreads();
        if (i + 3 < NSLAB) load_slab(i + 3, (i + 3) & 3);
        else CP_COMMIT();
        const uint32_t st = smb + (uint32_t)(i & 3) * STAGE;
#pragma unroll
        for (int kk = 0; kk < 2; ++kk) {
            uint32_t a[2][4];
            ldm_x4(a[0], st + aoff + kk * 32);
            ldm_x4(a[1], st + aoff + kk * 32 + 16 * PITCH);
            const uint32_t bb = st + OFF_B + boff + kk * 32;
#pragma unroll
            for (int nf2 = 0; nf2 < 4; ++nf2) {
                uint32_t b[4];
                ldm_x4(b, bb + nf2 * (16 * PITCH));
                mma_f16(acc[0][2*nf2],   a[0], b);
                mma_f16(acc[0][2*nf2+1], a[0], b + 2);
                mma_f16(acc[1][2*nf2],   a[1], b);
                mma_f16(acc[1][2*nf2+1], a[1], b + 2);
            }
        }
    }

#pragma unroll
    for (int mf = 0; mf < 2; ++mf) {
        int row = m0 + wm * 32 + mf * 16 + g;
#pragma unroll
        for (int nf = 0; nf < 8; ++nf) {
            int col = n0 + wn * 64 + nf * 8 + 2 * t;
            float b0 = bias[col], b1 = bias[col + 1];
            float2 o0 = make_float2(acc[mf][nf][0] + b0, acc[mf][nf][1] + b1);
            float2 o1 = make_float2(acc[mf][nf][2] + b0, acc[mf][nf][3] + b1);
            *(float2*)(C + (size_t)row * N + col)       = o0;
            *(float2*)(C + (size_t)(row + 8) * N + col) = o1;
        }
    }
}

// ---------------------------------------------------------------------------
// K2: qk_prep, warp-per-token (no block barriers).
// ---------------------------------------------------------------------------
__global__ __launch_bounds__(256) void qk_prep_k(const float* __restrict__ gq,
                                                 const float* __restrict__ gk)
{
    const int warp = threadIdx.x >> 5, lane = threadIdx.x & 31;
    const int t = blockIdx.x * 8 + warp;
    const int b = t >> 12;
    const int l = t & (Lq - 1);
    const float* row = g_qkv + (size_t)t * NQKV;
    float4 qv[8], kv[8];
    float sq = 0.0f, sk = 0.0f;
#pragma unroll
    for (int s = 0; s < 8; ++s) {
        qv[s] = *(const float4*)(row + lane * 4 + s * 128);
        kv[s] = *(const float4*)(row + Dq + lane * 4 + s * 128);
        sq += qv[s].x*qv[s].x + qv[s].y*qv[s].y + qv[s].z*qv[s].z + qv[s].w*qv[s].w;
        sk += kv[s].x*kv[s].x + kv[s].y*kv[s].y + kv[s].z*kv[s].z + kv[s].w*kv[s].w;
    }
#pragma unroll
    for (int o = 16; o > 0; o >>= 1) {
        sq += __shfl_xor_sync(0xffffffffu, sq, o);
        sk += __shfl_xor_sync(0xffffffffu, sk, o);
    }
    const float scq = rsqrtf(sq * (1.0f / 1024.0f) + RMSEPS);
    const float sck = rsqrtf(sk * (1.0f / 1024.0f) + RMSEPS);
#pragma unroll
    for (int s = 0; s < 8; ++s) {
        const int c0 = lane * 4 + s * 128;
        float4 gq4 = *(const float4*)(gq + c0);
        float4 gk4 = *(const float4*)(gk + c0);
        float qe[4] = {qv[s].x*scq*gq4.x, qv[s].y*scq*gq4.y, qv[s].z*scq*gq4.z, qv[s].w*scq*gq4.w};
        float ke[4] = {kv[s].x*sck*gk4.x, kv[s].y*sck*gk4.y, kv[s].z*sck*gk4.z, kv[s].w*sck*gk4.w};
#pragma unroll
        for (int p = 0; p < 2; ++p) {
            int d = (c0 + 2 * p) & 63;
            int j = d >> 1;
            float c = g_cos[l * 32 + j];
            float sn = g_sin[l * 32 + j];
            float q0 = qe[2*p], q1 = qe[2*p + 1];
            qe[2*p]     = q0 * c - q1 * sn;
            qe[2*p + 1] = q0 * sn + q1 * c;
            float k0 = ke[2*p], k1 = ke[2*p + 1];
            ke[2*p]     = k0 * c - k1 * sn;
            ke[2*p + 1] = k0 * sn + k1 * c;
        }
        const int h = c0 >> 6, d0 = c0 & 63;
        const size_t off = (((size_t)(b * Hq + h) * Lq) + l) * DHq + d0;
        uint2 qo, ko;
        *(__half2*)&qo.x = __floats2half2_rn(fmaxf(qe[0],0.f), fmaxf(qe[1],0.f));
        *(__half2*)&qo.y = __floats2half2_rn(fmaxf(qe[2],0.f), fmaxf(qe[3],0.f));
        *(__half2*)&ko.x = __floats2half2_rn(fmaxf(ke[0],0.f), fmaxf(ke[1],0.f));
        *(__half2*)&ko.y = __floats2half2_rn(fmaxf(ke[2],0.f), fmaxf(ke[3],0.f));
        *(uint2*)(g_qfh + off) = qo;
        *(uint2*)(g_kfh + off) = ko;
    }
}

// ---------------------------------------------------------------------------
// K3: vk partials, register-staged + double-buffered smem (1 barrier/sub).
// CTA = (bh, Lchunk of 256 tokens).
// ---------------------------------------------------------------------------
__global__ __launch_bounds__(256) void vk_accum_k() {
    const int bh = blockIdx.x;
    const int chunk = blockIdx.y;
    const int b = bh >> 4, h = bh & 15;
    const int tid = threadIdx.x;
    __shared__ __align__(16) float kf_s[2][32 * 64];
    __shared__ __align__(16) float vp_s[2][32 * 64];
    const int pq = tid >> 4;
    const int dq = tid & 15;
    float acc[4][4];
    float den[4] = {0.f, 0.f, 0.f, 0.f};
#pragma unroll
    for (int i = 0; i < 4; ++i)
#pragma unroll
        for (int j = 0; j < 4; ++j) acc[i][j] = 0.0f;

    const int l0 = chunk * (Lq / NCHUNK);
    const int tok0 = b * Lq + l0;
    const int r0 = tid >> 4;
    const int c4 = (tid & 15) << 2;
    const int lr  = tid >> 3;
    const int lc8 = (tid & 7) << 3;

    uint4 kraw;
    float4 vst0, vst1;
    auto ldg_sub = [&](int sub) {
        kraw = *(const uint4*)(g_kfh + ((size_t)bh * Lq + l0 + sub * 32 + lr) * DHq + lc8);
        vst0 = *(const float4*)(g_qkv + (size_t)(tok0 + sub * 32 + r0) * NQKV + 2 * Dq + h * DHq + c4);
        vst1 = *(const float4*)(g_qkv + (size_t)(tok0 + sub * 32 + r0 + 16) * NQKV + 2 * Dq + h * DHq + c4);
    };
    ldg_sub(0);

    const int NSUB = (Lq / NCHUNK) / 32;   // 8
#pragma unroll 1
    for (int sub = 0; sub < NSUB; ++sub) {
        const int bufi = sub & 1;
        {
            float2 f0 = __half22float2(*(__half2*)&kraw.x);
            float2 f1 = __half22float2(*(__half2*)&kraw.y);
            float2 f2 = __half22float2(*(__half2*)&kraw.z);
            float2 f3 = __half22float2(*(__half2*)&kraw.w);
            *(float4*)&kf_s[bufi][lr * 64 + lc8]     = make_float4(f0.x, f0.y, f1.x, f1.y);
            *(float4*)&kf_s[bufi][lr * 64 + lc8 + 4] = make_float4(f2.x, f2.y, f3.x, f3.y);
            *(float4*)&vp_s[bufi][r0 * 64 + c4]        = vst0;
            *(float4*)&vp_s[bufi][(r0 + 16) * 64 + c4] = vst1;
        }
        __syncthreads();
        if (sub + 1 < NSUB) ldg_sub(sub + 1);
#pragma unroll 8
        for (int r = 0; r < 32; ++r) {
            float4 vp = *(const float4*)&vp_s[bufi][r * 64 + pq * 4];
            float4 kf = *(const float4*)&kf_s[bufi][r * 64 + dq * 4];
            const float kfe[4] = {kf.x, kf.y, kf.z, kf.w};
            const float vpe[4] = {vp.x, vp.y, vp.z, vp.w};
#pragma unroll
            for (int i = 0; i < 4; ++i)
#pragma unroll
                for (int j = 0; j < 4; ++j)
                    acc[i][j] = fmaf(vpe[i], kfe[j], acc[i][j]);
            if (pq == 0) {
#pragma unroll
                for (int j = 0; j < 4; ++j) den[j] += kfe[j];
            }
        }
        // no trailing barrier: next store targets the other buffer, whose last
        // readers all passed the barrier above.
    }
    float* dst = g_vkp + (size_t)chunk * (64 * 65 * 64) + bh * (65 * 64);
#pragma unroll
    for (int i = 0; i < 4; ++i) {
        float4 o = make_float4(acc[i][0], acc[i][1], acc[i][2], acc[i][3]);
        *(float4*)(dst + (pq * 4 + i) * 64 + dq * 4) = o;
    }
    if (pq == 0)
        *(float4*)(dst + 64 * 64 + dq * 4) = make_float4(den[0], den[1], den[2], den[3]);
}

// K4: deterministic reduce; num rows -> fp16 g_vkh, den row -> fp32 g_vkden.
__global__ void vk_reduce_k() {
    int i = blockIdx.x * 256 + threadIdx.x;
    if (i >= 64 * 65 * 64) return;
    float s = 0.0f;
#pragma unroll
    for (int c = 0; c < NCHUNK; ++c) s += g_vkp[(size_t)c * (64 * 65 * 64) + i];
    const int bh = i / (65 * 64);
    const int rem = i - bh * (65 * 64);
    const int p = rem >> 6, d = rem & 63;
    if (p < 64) g_vkh[(size_t)bh * 4096 + p * 64 + d] = __float2half_rn(s);
    else        g_vkden[bh * 64 + d] = s;
}

// ---------------------------------------------------------------------------
// K5: attn via HMMA. CTA = (bh, 64-token tile).
// num[tok][p] = sum_d vk[p][d]*qf[tok][d]  (fp16 MMA, fp32 acc)
// den[tok]    = sum_d vkden[d]*qf[tok][d]  (fp32)
// out = num/(den+eps) -> fp16 g_ah.
// ---------------------------------------------------------------------------
#define QP 72   // smem pitch in halves (144 B): 16B-aligned, conflict-free ldmatrix
__global__ __launch_bounds__(256) void attn_hmma_k() {
    const int bh = blockIdx.x;
    const int lt = blockIdx.y;
    const int b = bh >> 4, h = bh & 15;
    const int tid = threadIdx.x;
    __shared__ __align__(16) __half qf_h[64 * QP];
    __shared__ __align__(16) __half vk_h[64 * QP];
    __shared__ float den_row[64];
    __shared__ float den_s[64];

    // load qf tile (64x64 fp16) and vk tile (64x64 fp16)
    {
        const __half* qsrc = g_qfh + ((size_t)bh * Lq + lt * 64) * DHq;
        const __half* vsrc = g_vkh + (size_t)bh * 4096;
#pragma unroll
        for (int j = 0; j < 2; ++j) {
            int chunk = tid + j * 256;          // 512 chunks of 8 halves
            int r = chunk >> 3, c8 = (chunk & 7) << 3;
            *(uint4*)&qf_h[r * QP + c8] = *(const uint4*)(qsrc + r * 64 + c8);
            *(uint4*)&vk_h[r * QP + c8] = *(const uint4*)(vsrc + r * 64 + c8);
        }
        if (tid < 64) den_row[tid] = g_vkden[bh * 64 + tid];
    }
    __syncthreads();

    // den per token (fp32 path)
    if (tid < 64) {
        float d = 0.0f;
#pragma unroll
        for (int k = 0; k < 64; ++k)
            d = fmaf(den_row[k], __half2float(qf_h[tid * QP + k]), d);
        den_s[tid] = d;
    }

    // HMMA: 8 warps = 4(tok) x 2(p); warp tile 16 tok x 32 p; K = 64.
    const int wid = tid >> 5, lane = tid & 31;
    const int wm = wid & 3, wn = wid >> 2;
    const int quad = lane >> 3, r8 = lane & 7;
    const int g = lane >> 2, t = lane & 3;
    const uint32_t qb = smem_u32(qf_h);
    const uint32_t vb = smem_u32(vk_h);
    const uint32_t aoff = (uint32_t)((wm * 16 + (quad & 1) * 8 + r8) * (QP * 2) + (quad >> 1) * 16);
    const uint32_t boff = (uint32_t)((wn * 32 + (quad >> 1) * 8 + r8) * (QP * 2) + (quad & 1) * 16);
    float acc[4][4];
#pragma unroll
    for (int i = 0; i < 4; ++i)
#pragma unroll
        for (int j = 0; j < 4; ++j) acc[i][j] = 0.0f;
#pragma unroll
    for (int kk = 0; kk < 4; ++kk) {
        uint32_t a[4];
        ldm_x4(a, qb + aoff + kk * 32);
#pragma unroll
        for (int nf2 = 0; nf2 < 2; ++nf2) {
            uint32_t bfr[4];
            ldm_x4(bfr, vb + boff + nf2 * (16 * QP * 2) + kk * 32);
            mma_f16(acc[2*nf2],     a, bfr);
            mma_f16(acc[2*nf2 + 1], a, bfr + 2);
        }
    }
    __syncthreads();   // den_s ready

    // epilogue: divide + fp16 store
#pragma unroll
    for (int nf = 0; nf < 4; ++nf) {
        const int p = wn * 32 + nf * 8 + 2 * t;
        const int tok0 = wm * 16 + g;
        const float d0 = den_s[tok0] + EPSLIN;
        const float d1 = den_s[tok0 + 8] + EPSLIN;
        __half2 o0 = __floats2half2_rn(acc[nf][0] / d0, acc[nf][1] / d0);
        __half2 o1 = __floats2half2_rn(acc[nf][2] / d1, acc[nf][3] / d1);
        *(__half2*)(g_ah + (size_t)(b * Lq + lt * 64 + tok0) * Dq + h * DHq + p)     = o0;
        *(__half2*)(g_ah + (size_t)(b * Lq + lt * 64 + tok0 + 8) * Dq + h * DHq + p) = o1;
    }
}

// ---------------------------------------------------------------------------
// K7: final rmsnorm, warp-per-token.
// ---------------------------------------------------------------------------
__global__ __launch_bounds__(256) void out_rms_k(const float* __restrict__ gout,
                                                 float* __restrict__ out)
{
    const int warp = threadIdx.x >> 5, lane = threadIdx.x & 31;
    const int t = blockIdx.x * 8 + warp;
    const float* row = g_y + (size_t)t * Dq;
    float4 y[8];
    float ss = 0.0f;
#pragma unroll
    for (int s = 0; s < 8; ++s) {
        y[s] = *(const float4*)(row + lane * 4 + s * 128);
        ss += y[s].x*y[s].x + y[s].y*y[s].y + y[s].z*y[s].z + y[s].w*y[s].w;
    }
#pragma unroll
    for (int o = 16; o > 0; o >>= 1) ss += __shfl_xor_sync(0xffffffffu, ss, o);
    const float sc = rsqrtf(ss * (1.0f / 1024.0f) + RMSEPS);
#pragma unroll
    for (int s = 0; s < 8; ++s) {
        const int c0 = lane * 4 + s * 128;
        float4 gg = *(const float4*)(gout + c0);
        float4 o4;
        o4.x = y[s].x * sc * gg.x;
        o4.y = y[s].y * sc * gg.y;
        o4.z = y[s].z * sc * gg.z;
        o4.w = y[s].w * sc * gg.w;
        *(float4*)(out + (size_t)t * Dq + c0) = o4;
    }
}

// ---------------------------------------------------------------------------
extern "C" void kernel_launch(void* const* d_in, const int* in_sizes, int n_in,
                              void* d_out, int out_size) {
    (void)in_sizes; (void)n_in; (void)out_size;
    const float* x    = (const float*)d_in[0];
    const float* Wqkv = (const float*)d_in[1];
    const float* bqkv = (const float*)d_in[2];
    const float* gq   = (const float*)d_in[3];
    const float* gk   = (const float*)d_in[4];
    const float* Wout = (const float*)d_in[5];
    const float* bout = (const float*)d_in[6];
    const float* gout = (const float*)d_in[7];
    float* out = (float*)d_out;

    float *qkv_p, *y_p;
    __half *xh, *ah, *wh1, *wh2;
    cudaGetSymbolAddress((void**)&qkv_p, g_qkv);
    cudaGetSymbolAddress((void**)&y_p,   g_y);
    cudaGetSymbolAddress((void**)&xh,  g_xh);
    cudaGetSymbolAddress((void**)&ah,  g_ah);
    cudaGetSymbolAddress((void**)&wh1, g_wh1);
    cudaGetSymbolAddress((void**)&wh2, g_wh2);

    const int DSMEM = NSTG * STAGE;   // 81920
    cudaFuncSetAttribute(gemm_hmma3_k, cudaFuncAttributeMaxDynamicSharedMemorySize, DSMEM);

    prep_fused_k<<<NB_ROPE + NB_X + NB_W1 + NB_W2, 256>>>(x, Wqkv, Wout, xh, wh1, wh2); // 0
    gemm_hmma3_k<<<dim3(NQKV / 128, MTOK / 128), 256, DSMEM>>>(                          // 1
        xh, wh1, bqkv, qkv_p, NQKV);
    qk_prep_k<<<MTOK / 8, 256>>>(gq, gk);                                                // 2
    vk_accum_k<<<dim3(64, NCHUNK), 256>>>();                                             // 3 (profiled)
    vk_reduce_k<<<(64 * 65 * 64 + 255) / 256, 256>>>();
    attn_hmma_k<<<dim3(64, 64), 256>>>();
    gemm_hmma3_k<<<dim3(Dq / 128, MTOK / 128), 256, DSMEM>>>(
        ah, wh2, bout, y_p, Dq);
    out_rms_k<<<MTOK / 8, 256>>>(gout, out);
}

// round 14
// speedup vs baseline: 1.7671x; 1.0057x over previous
#include <cuda_runtime.h>
#include <cuda_fp16.h>
#include <math.h>
#include <stdint.h>

// Problem constants
#define Bq    4
#define Lq    4096
#define Dq    1024
#define Hq    16
#define DHq   64
#define MTOK  (Bq*Lq)      // 16384
#define NQKV  (3*Dq)       // 3072
#define RMSEPS 1.1920929e-07f
#define EPSLIN 1e-06f
#define NCHUNK 16

// Scratch (device globals — no allocation allowed)
__device__ __align__(256) float g_qkv [(size_t)MTOK * NQKV];   // fp32 qkv (v read later)
__device__ __align__(256) float g_vkp [NCHUNK * 64 * 65 * DHq];
__device__ __align__(256) float g_vkden[64 * DHq];             // den row (p=64), fp32
__device__ __align__(256) float g_y   [(size_t)MTOK * Dq];
__device__ __align__(256) float g_cos [Lq * 32];
__device__ __align__(256) float g_sin [Lq * 32];
// fp16 operands / intermediates
__device__ __align__(256) __half g_xh [(size_t)MTOK * Dq];
__device__ __align__(256) __half g_ah [(size_t)MTOK * Dq];    // attn in fp16 (gemm2 A)
__device__ __align__(256) __half g_wh1[(size_t)NQKV * Dq];
__device__ __align__(256) __half g_wh2[(size_t)Dq * Dq];
__device__ __align__(256) __half g_qfh[(size_t)MTOK * Dq];    // qf, head-major [bh][l][64]
__device__ __align__(256) __half g_kfh[(size_t)MTOK * Dq];    // kf, head-major [bh][l][64]
__device__ __align__(256) __half g_vkh[64 * 64 * DHq];        // vk rows 0..63, fp16 [bh][p][d]

// ---------------------------------------------------------------------------
__device__ __forceinline__ uint32_t smem_u32(const void* p) {
    uint32_t a;
    asm("{ .reg .u64 t; cvta.to.shared.u64 t, %1; cvt.u32.u64 %0, t; }" : "=r"(a) : "l"(p));
    return a;
}
__device__ __forceinline__ void cp_async16(uint32_t dst, const void* src) {
    asm volatile("cp.async.cg.shared.global [%0], [%1], 16;" :: "r"(dst), "l"(src));
}
#define CP_COMMIT() asm volatile("cp.async.commit_group;" ::: "memory")
template <int N>
__device__ __forceinline__ void cp_wait() {
    asm volatile("cp.async.wait_group %0;" :: "n"(N) : "memory");
}
__device__ __forceinline__ void ldm_x4(uint32_t* r, uint32_t addr) {
    asm volatile("ldmatrix.sync.aligned.m8n8.x4.shared.b16 {%0,%1,%2,%3}, [%4];"
                 : "=r"(r[0]), "=r"(r[1]), "=r"(r[2]), "=r"(r[3]) : "r"(addr));
}
__device__ __forceinline__ void mma_f16(float* c, const uint32_t* a, const uint32_t* b) {
    asm volatile(
        "mma.sync.aligned.m16n8k16.row.col.f32.f16.f16.f32 "
        "{%0,%1,%2,%3}, {%4,%5,%6,%7}, {%8,%9}, {%0,%1,%2,%3};"
        : "+f"(c[0]), "+f"(c[1]), "+f"(c[2]), "+f"(c[3])
        : "r"(a[0]), "r"(a[1]), "r"(a[2]), "r"(a[3]), "r"(b[0]), "r"(b[1]));
}
// Packed fp32 pair ops (Blackwell f32x2)
__device__ __forceinline__ void ffma2(uint64_t& c, uint64_t a, uint64_t b) {
    asm("fma.rn.f32x2 %0, %1, %2, %0;" : "+l"(c) : "l"(a), "l"(b));
}
__device__ __forceinline__ void fadd2(uint64_t& c, uint64_t a) {
    asm("add.rn.f32x2 %0, %0, %1;" : "+l"(c) : "l"(a));
}
__device__ __forceinline__ uint64_t dup2(uint32_t x) {
    uint64_t r; asm("mov.b64 %0, {%1, %1};" : "=l"(r) : "r"(x)); return r;
}
__device__ __forceinline__ uint64_t pack2(uint32_t lo, uint32_t hi) {
    uint64_t r; asm("mov.b64 %0, {%1, %2};" : "=l"(r) : "r"(lo), "r"(hi)); return r;
}

// ---------------------------------------------------------------------------
// K0: fused prep — rope tables + three fp32->fp16 conversions, grid-partitioned.
// ---------------------------------------------------------------------------
__device__ __forceinline__ void conv4(const float* __restrict__ s,
                                      __half* __restrict__ d, int i) {
    float4 v = ((const float4*)s)[i];
    ((__half2*)d)[2*i]   = __floats2half2_rn(v.x, v.y);
    ((__half2*)d)[2*i+1] = __floats2half2_rn(v.z, v.w);
}
#define NB_ROPE 512
#define NB_X    16384
#define NB_W1   3072
#define NB_W2   1024
__global__ __launch_bounds__(256) void prep_fused_k(
    const float* __restrict__ x, const float* __restrict__ W1,
    const float* __restrict__ W2,
    __half* __restrict__ xh, __half* __restrict__ wh1, __half* __restrict__ wh2)
{
    const int bid = blockIdx.x;
    const int tid = threadIdx.x;
    if (bid < NB_ROPE) {
        int idx = bid * 256 + tid;
        int l = idx >> 5, j = idx & 31;
        float inv_freq = expf(-(float)j * (9.210340371976184f / 32.0f));
        float ang = (float)l * inv_freq;
        g_cos[idx] = cosf(ang);
        g_sin[idx] = sinf(ang);
    } else if (bid < NB_ROPE + NB_X) {
        conv4(x, xh, (bid - NB_ROPE) * 256 + tid);
    } else if (bid < NB_ROPE + NB_X + NB_W1) {
        conv4(W1, wh1, (bid - NB_ROPE - NB_X) * 256 + tid);
    } else {
        conv4(W2, wh2, (bid - NB_ROPE - NB_X - NB_W1) * 256 + tid);
    }
}

// ---------------------------------------------------------------------------
// HMMA GEMM (R9-frozen): C[m,n] = sum_k A[m,k]*B[n,k] + bias[n], K = 1024.
// ---------------------------------------------------------------------------
#define BKS     32
#define NSLAB   32
#define PITCH   80
#define TILEB   (128 * PITCH)
#define OFF_B   TILEB
#define STAGE   (2 * TILEB)
#define NSTG    4

__global__ __launch_bounds__(256, 2)
void gemm_hmma3_k(const __half* __restrict__ A, const __half* __restrict__ B,
                  const float* __restrict__ bias, float* __restrict__ C, int N)
{
    extern __shared__ __align__(16) char sm[];
    const uint32_t smb = smem_u32(sm);
    const int tid  = threadIdx.x;
    const int wid  = tid >> 5, lane = tid & 31;
    const int wm   = wid & 3, wn = wid >> 2;
    const int g    = lane >> 2, t = lane & 3;
    const int m0   = blockIdx.y * 128;
    const int n0   = blockIdx.x * 128;

    float acc[2][8][4];
#pragma unroll
    for (int mf = 0; mf < 2; ++mf)
#pragma unroll
        for (int nf = 0; nf < 8; ++nf)
#pragma unroll
            for (int e = 0; e < 4; ++e) acc[mf][nf][e] = 0.0f;

    const int crow = tid >> 2;
    const int c16  = tid & 3;
    auto load_slab = [&](int ks, int st) {
        uint32_t base = smb + st * STAGE;
#pragma unroll
        for (int j = 0; j < 2; ++j) {
            int row = crow + j * 64;
            uint32_t d = base + row * PITCH + c16 * 16;
            cp_async16(d,         A + (size_t)(m0 + row) * 1024 + ks * BKS + c16 * 8);
            cp_async16(d + OFF_B, B + (size_t)(n0 + row) * 1024 + ks * BKS + c16 * 8);
        }
        CP_COMMIT();
    };

    const int quad = lane >> 3, r8 = lane & 7;
    const uint32_t aoff = (uint32_t)((wm * 32 + (quad & 1) * 8 + r8) * PITCH + (quad >> 1) * 16);
    const uint32_t boff = (uint32_t)((wn * 64 + (quad >> 1) * 8 + r8) * PITCH + (quad & 1) * 16);

    load_slab(0, 0);
    load_slab(1, 1);
    load_slab(2, 2);

#pragma unroll 1
    for (int i = 0; i < NSLAB; ++i) {
        cp_wait<2>();
        __syncthreads();
        if (i + 3 < NSLAB) load_slab(i + 3, (i + 3) & 3);
        else CP_COMMIT();
        const uint32_t st = smb + (uint32_t)(i & 3) * STAGE;
#pragma unroll
        for (int kk = 0; kk < 2; ++kk) {
            uint32_t a[2][4];
            ldm_x4(a[0], st + aoff + kk * 32);
            ldm_x4(a[1], st + aoff + kk * 32 + 16 * PITCH);
            const uint32_t bb = st + OFF_B + boff + kk * 32;
#pragma unroll
            for (int nf2 = 0; nf2 < 4; ++nf2) {
                uint32_t b[4];
                ldm_x4(b, bb + nf2 * (16 * PITCH));
                mma_f16(acc[0][2*nf2],   a[0], b);
                mma_f16(acc[0][2*nf2+1], a[0], b + 2);
                mma_f16(acc[1][2*nf2],   a[1], b);
                mma_f16(acc[1][2*nf2+1], a[1], b + 2);
            }
        }
    }

#pragma unroll
    for (int mf = 0; mf < 2; ++mf) {
        int row = m0 + wm * 32 + mf * 16 + g;
#pragma unroll
        for (int nf = 0; nf < 8; ++nf) {
            int col = n0 + wn * 64 + nf * 8 + 2 * t;
            float b0 = bias[col], b1 = bias[col + 1];
            float2 o0 = make_float2(acc[mf][nf][0] + b0, acc[mf][nf][1] + b1);
            float2 o1 = make_float2(acc[mf][nf][2] + b0, acc[mf][nf][3] + b1);
            *(float2*)(C + (size_t)row * N + col)       = o0;
            *(float2*)(C + (size_t)(row + 8) * N + col) = o1;
        }
    }
}

// ---------------------------------------------------------------------------
// K2: qk_prep, warp-per-token (no block barriers).
// ---------------------------------------------------------------------------
__global__ __launch_bounds__(256) void qk_prep_k(const float* __restrict__ gq,
                                                 const float* __restrict__ gk)
{
    const int warp = threadIdx.x >> 5, lane = threadIdx.x & 31;
    const int t = blockIdx.x * 8 + warp;
    const int b = t >> 12;
    const int l = t & (Lq - 1);
    const float* row = g_qkv + (size_t)t * NQKV;
    float4 qv[8], kv[8];
    float sq = 0.0f, sk = 0.0f;
#pragma unroll
    for (int s = 0; s < 8; ++s) {
        qv[s] = *(const float4*)(row + lane * 4 + s * 128);
        kv[s] = *(const float4*)(row + Dq + lane * 4 + s * 128);
        sq += qv[s].x*qv[s].x + qv[s].y*qv[s].y + qv[s].z*qv[s].z + qv[s].w*qv[s].w;
        sk += kv[s].x*kv[s].x + kv[s].y*kv[s].y + kv[s].z*kv[s].z + kv[s].w*kv[s].w;
    }
#pragma unroll
    for (int o = 16; o > 0; o >>= 1) {
        sq += __shfl_xor_sync(0xffffffffu, sq, o);
        sk += __shfl_xor_sync(0xffffffffu, sk, o);
    }
    const float scq = rsqrtf(sq * (1.0f / 1024.0f) + RMSEPS);
    const float sck = rsqrtf(sk * (1.0f / 1024.0f) + RMSEPS);
#pragma unroll
    for (int s = 0; s < 8; ++s) {
        const int c0 = lane * 4 + s * 128;
        float4 gq4 = *(const float4*)(gq + c0);
        float4 gk4 = *(const float4*)(gk + c0);
        float qe[4] = {qv[s].x*scq*gq4.x, qv[s].y*scq*gq4.y, qv[s].z*scq*gq4.z, qv[s].w*scq*gq4.w};
        float ke[4] = {kv[s].x*sck*gk4.x, kv[s].y*sck*gk4.y, kv[s].z*sck*gk4.z, kv[s].w*sck*gk4.w};
#pragma unroll
        for (int p = 0; p < 2; ++p) {
            int d = (c0 + 2 * p) & 63;
            int j = d >> 1;
            float c = g_cos[l * 32 + j];
            float sn = g_sin[l * 32 + j];
            float q0 = qe[2*p], q1 = qe[2*p + 1];
            qe[2*p]     = q0 * c - q1 * sn;
            qe[2*p + 1] = q0 * sn + q1 * c;
            float k0 = ke[2*p], k1 = ke[2*p + 1];
            ke[2*p]     = k0 * c - k1 * sn;
            ke[2*p + 1] = k0 * sn + k1 * c;
        }
        const int h = c0 >> 6, d0 = c0 & 63;
        const size_t off = (((size_t)(b * Hq + h) * Lq) + l) * DHq + d0;
        uint2 qo, ko;
        *(__half2*)&qo.x = __floats2half2_rn(fmaxf(qe[0],0.f), fmaxf(qe[1],0.f));
        *(__half2*)&qo.y = __floats2half2_rn(fmaxf(qe[2],0.f), fmaxf(qe[3],0.f));
        *(__half2*)&ko.x = __floats2half2_rn(fmaxf(ke[0],0.f), fmaxf(ke[1],0.f));
        *(__half2*)&ko.y = __floats2half2_rn(fmaxf(ke[2],0.f), fmaxf(ke[3],0.f));
        *(uint2*)(g_qfh + off) = qo;
        *(uint2*)(g_kfh + off) = ko;
    }
}

// ---------------------------------------------------------------------------
// K3: vk partials, f32x2-packed FMA, double-buffered smem (1 barrier/sub).
// Thread (pq,dq) owns 4x4 (p,d); acc packed as 4 rows x 2 f32-pairs.
// ---------------------------------------------------------------------------
__global__ __launch_bounds__(256) void vk_accum_k() {
    const int bh = blockIdx.x;
    const int chunk = blockIdx.y;
    const int b = bh >> 4, h = bh & 15;
    const int tid = threadIdx.x;
    __shared__ __align__(16) float kf_s[2][32 * 64];
    __shared__ __align__(16) float vp_s[2][32 * 64];
    const int pq = tid >> 4;
    const int dq = tid & 15;
    uint64_t acc2[4][2];
    uint64_t den2[2] = {0ull, 0ull};
#pragma unroll
    for (int i = 0; i < 4; ++i) { acc2[i][0] = 0ull; acc2[i][1] = 0ull; }

    const int l0 = chunk * (Lq / NCHUNK);
    const int tok0 = b * Lq + l0;
    const int r0 = tid >> 4;
    const int c4 = (tid & 15) << 2;
    const int lr  = tid >> 3;
    const int lc8 = (tid & 7) << 3;

    uint4 kraw;
    float4 vst0, vst1;
    auto ldg_sub = [&](int sub) {
        kraw = *(const uint4*)(g_kfh + ((size_t)bh * Lq + l0 + sub * 32 + lr) * DHq + lc8);
        vst0 = *(const float4*)(g_qkv + (size_t)(tok0 + sub * 32 + r0) * NQKV + 2 * Dq + h * DHq + c4);
        vst1 = *(const float4*)(g_qkv + (size_t)(tok0 + sub * 32 + r0 + 16) * NQKV + 2 * Dq + h * DHq + c4);
    };
    ldg_sub(0);

    const int NSUB = (Lq / NCHUNK) / 32;   // 8
#pragma unroll 1
    for (int sub = 0; sub < NSUB; ++sub) {
        const int bufi = sub & 1;
        {
            float2 f0 = __half22float2(*(__half2*)&kraw.x);
            float2 f1 = __half22float2(*(__half2*)&kraw.y);
            float2 f2 = __half22float2(*(__half2*)&kraw.z);
            float2 f3 = __half22float2(*(__half2*)&kraw.w);
            *(float4*)&kf_s[bufi][lr * 64 + lc8]     = make_float4(f0.x, f0.y, f1.x, f1.y);
            *(float4*)&kf_s[bufi][lr * 64 + lc8 + 4] = make_float4(f2.x, f2.y, f3.x, f3.y);
            *(float4*)&vp_s[bufi][r0 * 64 + c4]        = vst0;
            *(float4*)&vp_s[bufi][(r0 + 16) * 64 + c4] = vst1;
        }
        __syncthreads();
        if (sub + 1 < NSUB) ldg_sub(sub + 1);
#pragma unroll 8
        for (int r = 0; r < 32; ++r) {
            uint4 vpr = *(const uint4*)&vp_s[bufi][r * 64 + pq * 4];
            uint4 kfr = *(const uint4*)&kf_s[bufi][r * 64 + dq * 4];
            uint64_t kf01 = pack2(kfr.x, kfr.y);
            uint64_t kf23 = pack2(kfr.z, kfr.w);
            uint64_t vd0 = dup2(vpr.x), vd1 = dup2(vpr.y);
            uint64_t vd2 = dup2(vpr.z), vd3 = dup2(vpr.w);
            ffma2(acc2[0][0], vd0, kf01); ffma2(acc2[0][1], vd0, kf23);
            ffma2(acc2[1][0], vd1, kf01); ffma2(acc2[1][1], vd1, kf23);
            ffma2(acc2[2][0], vd2, kf01); ffma2(acc2[2][1], vd2, kf23);
            ffma2(acc2[3][0], vd3, kf01); ffma2(acc2[3][1], vd3, kf23);
            if (pq == 0) { fadd2(den2[0], kf01); fadd2(den2[1], kf23); }
        }
        // no trailing barrier: next store targets the other buffer, whose last
        // readers all passed the barrier above.
    }
    float* dst = g_vkp + (size_t)chunk * (64 * 65 * 64) + bh * (65 * 64);
#pragma unroll
    for (int i = 0; i < 4; ++i) {
        uint4 o;
        o.x = (uint32_t)(acc2[i][0]);  o.y = (uint32_t)(acc2[i][0] >> 32);
        o.z = (uint32_t)(acc2[i][1]);  o.w = (uint32_t)(acc2[i][1] >> 32);
        *(uint4*)(dst + (pq * 4 + i) * 64 + dq * 4) = o;
    }
    if (pq == 0) {
        uint4 o;
        o.x = (uint32_t)(den2[0]);  o.y = (uint32_t)(den2[0] >> 32);
        o.z = (uint32_t)(den2[1]);  o.w = (uint32_t)(den2[1] >> 32);
        *(uint4*)(dst + 64 * 64 + dq * 4) = o;
    }
}

// K4: deterministic reduce; num rows -> fp16 g_vkh, den row -> fp32 g_vkden.
__global__ void vk_reduce_k() {
    int i = blockIdx.x * 256 + threadIdx.x;
    if (i >= 64 * 65 * 64) return;
    float s = 0.0f;
#pragma unroll
    for (int c = 0; c < NCHUNK; ++c) s += g_vkp[(size_t)c * (64 * 65 * 64) + i];
    const int bh = i / (65 * 64);
    const int rem = i - bh * (65 * 64);
    const int p = rem >> 6, d = rem & 63;
    if (p < 64) g_vkh[(size_t)bh * 4096 + p * 64 + d] = __float2half_rn(s);
    else        g_vkden[bh * 64 + d] = s;
}

// ---------------------------------------------------------------------------
// K5: attn via HMMA. CTA = (bh, 64-token tile).
// ---------------------------------------------------------------------------
#define QP 72   // smem pitch in halves (144 B)
__global__ __launch_bounds__(256) void attn_hmma_k() {
    const int bh = blockIdx.x;
    const int lt = blockIdx.y;
    const int b = bh >> 4, h = bh & 15;
    const int tid = threadIdx.x;
    __shared__ __align__(16) __half qf_h[64 * QP];
    __shared__ __align__(16) __half vk_h[64 * QP];
    __shared__ float den_row[64];
    __shared__ float den_s[64];

    {
        const __half* qsrc = g_qfh + ((size_t)bh * Lq + lt * 64) * DHq;
        const __half* vsrc = g_vkh + (size_t)bh * 4096;
#pragma unroll
        for (int j = 0; j < 2; ++j) {
            int chunk = tid + j * 256;
            int r = chunk >> 3, c8 = (chunk & 7) << 3;
            *(uint4*)&qf_h[r * QP + c8] = *(const uint4*)(qsrc + r * 64 + c8);
            *(uint4*)&vk_h[r * QP + c8] = *(const uint4*)(vsrc + r * 64 + c8);
        }
        if (tid < 64) den_row[tid] = g_vkden[bh * 64 + tid];
    }
    __syncthreads();

    if (tid < 64) {
        float d = 0.0f;
#pragma unroll
        for (int k = 0; k < 64; ++k)
            d = fmaf(den_row[k], __half2float(qf_h[tid * QP + k]), d);
        den_s[tid] = d;
    }

    const int wid = tid >> 5, lane = tid & 31;
    const int wm = wid & 3, wn = wid >> 2;
    const int quad = lane >> 3, r8 = lane & 7;
    const int g = lane >> 2, t = lane & 3;
    const uint32_t qb = smem_u32(qf_h);
    const uint32_t vb = smem_u32(vk_h);
    const uint32_t aoff = (uint32_t)((wm * 16 + (quad & 1) * 8 + r8) * (QP * 2) + (quad >> 1) * 16);
    const uint32_t boff = (uint32_t)((wn * 32 + (quad >> 1) * 8 + r8) * (QP * 2) + (quad & 1) * 16);
    float acc[4][4];
#pragma unroll
    for (int i = 0; i < 4; ++i)
#pragma unroll
        for (int j = 0; j < 4; ++j) acc[i][j] = 0.0f;
#pragma unroll
    for (int kk = 0; kk < 4; ++kk) {
        uint32_t a[4];
        ldm_x4(a, qb + aoff + kk * 32);
#pragma unroll
        for (int nf2 = 0; nf2 < 2; ++nf2) {
            uint32_t bfr[4];
            ldm_x4(bfr, vb + boff + nf2 * (16 * QP * 2) + kk * 32);
            mma_f16(acc[2*nf2],     a, bfr);
            mma_f16(acc[2*nf2 + 1], a, bfr + 2);
        }
    }
    __syncthreads();

#pragma unroll
    for (int nf = 0; nf < 4; ++nf) {
        const int p = wn * 32 + nf * 8 + 2 * t;
        const int tok0 = wm * 16 + g;
        const float d0 = den_s[tok0] + EPSLIN;
        const float d1 = den_s[tok0 + 8] + EPSLIN;
        __half2 o0 = __floats2half2_rn(acc[nf][0] / d0, acc[nf][1] / d0);
        __half2 o1 = __floats2half2_rn(acc[nf][2] / d1, acc[nf][3] / d1);
        *(__half2*)(g_ah + (size_t)(b * Lq + lt * 64 + tok0) * Dq + h * DHq + p)     = o0;
        *(__half2*)(g_ah + (size_t)(b * Lq + lt * 64 + tok0 + 8) * Dq + h * DHq + p) = o1;
    }
}

// ---------------------------------------------------------------------------
// K7: final rmsnorm, warp-per-token.
// ---------------------------------------------------------------------------
__global__ __launch_bounds__(256) void out_rms_k(const float* __restrict__ gout,
                                                 float* __restrict__ out)
{
    const int warp = threadIdx.x >> 5, lane = threadIdx.x & 31;
    const int t = blockIdx.x * 8 + warp;
    const float* row = g_y + (size_t)t * Dq;
    float4 y[8];
    float ss = 0.0f;
#pragma unroll
    for (int s = 0; s < 8; ++s) {
        y[s] = *(const float4*)(row + lane * 4 + s * 128);
        ss += y[s].x*y[s].x + y[s].y*y[s].y + y[s].z*y[s].z + y[s].w*y[s].w;
    }
#pragma unroll
    for (int o = 16; o > 0; o >>= 1) ss += __shfl_xor_sync(0xffffffffu, ss, o);
    const float sc = rsqrtf(ss * (1.0f / 1024.0f) + RMSEPS);
#pragma unroll
    for (int s = 0; s < 8; ++s) {
        const int c0 = lane * 4 + s * 128;
        float4 gg = *(const float4*)(gout + c0);
        float4 o4;
        o4.x = y[s].x * sc * gg.x;
        o4.y = y[s].y * sc * gg.y;
        o4.z = y[s].z * sc * gg.z;
        o4.w = y[s].w * sc * gg.w;
        *(float4*)(out + (size_t)t * Dq + c0) = o4;
    }
}

// ---------------------------------------------------------------------------
extern "C" void kernel_launch(void* const* d_in, const int* in_sizes, int n_in,
                              void* d_out, int out_size) {
    (void)in_sizes; (void)n_in; (void)out_size;
    const float* x    = (const float*)d_in[0];
    const float* Wqkv = (const float*)d_in[1];
    const float* bqkv = (const float*)d_in[2];
    const float* gq   = (const float*)d_in[3];
    const float* gk   = (const float*)d_in[4];
    const float* Wout = (const float*)d_in[5];
    const float* bout = (const float*)d_in[6];
    const float* gout = (const float*)d_in[7];
    float* out = (float*)d_out;

    float *qkv_p, *y_p;
    __half *xh, *ah, *wh1, *wh2;
    cudaGetSymbolAddress((void**)&qkv_p, g_qkv);
    cudaGetSymbolAddress((void**)&y_p,   g_y);
    cudaGetSymbolAddress((void**)&xh,  g_xh);
    cudaGetSymbolAddress((void**)&ah,  g_ah);
    cudaGetSymbolAddress((void**)&wh1, g_wh1);
    cudaGetSymbolAddress((void**)&wh2, g_wh2);

    const int DSMEM = NSTG * STAGE;   // 81920
    cudaFuncSetAttribute(gemm_hmma3_k, cudaFuncAttributeMaxDynamicSharedMemorySize, DSMEM);

    prep_fused_k<<<NB_ROPE + NB_X + NB_W1 + NB_W2, 256>>>(x, Wqkv, Wout, xh, wh1, wh2); // 0
    gemm_hmma3_k<<<dim3(NQKV / 128, MTOK / 128), 256, DSMEM>>>(                          // 1
        xh, wh1, bqkv, qkv_p, NQKV);
    qk_prep_k<<<MTOK / 8, 256>>>(gq, gk);                                                // 2
    vk_accum_k<<<dim3(64, NCHUNK), 256>>>();                                             // 3 (profiled)
    vk_reduce_k<<<(64 * 65 * 64 + 255) / 256, 256>>>();
    attn_hmma_k<<<dim3(64, 64), 256>>>();
    gemm_hmma3_k<<<dim3(Dq / 128, MTOK / 128), 256, DSMEM>>>(
        ah, wh2, bout, y_p, Dq);
    out_rms_k<<<MTOK / 8, 256>>>(gout, out);
}

// round 15
// speedup vs baseline: 1.8572x; 1.0510x over previous
#include <cuda_runtime.h>
#include <cuda_fp16.h>
#include <math.h>
#include <stdint.h>

// Problem constants
#define Bq    4
#define Lq    4096
#define Dq    1024
#define Hq    16
#define DHq   64
#define MTOK  (Bq*Lq)      // 16384
#define NQKV  (3*Dq)       // 3072
#define RMSEPS 1.1920929e-07f
#define EPSLIN 1e-06f
#define NCHUNK 16

// Scratch (device globals — no allocation allowed)
__device__ __align__(256) float g_qkv [(size_t)MTOK * NQKV];   // fp32 qkv (v read later)
__device__ __align__(256) float g_vkp [NCHUNK * 64 * 65 * DHq];
__device__ __align__(256) float g_vkden[64 * DHq];             // den row (p=64), fp32
__device__ __align__(256) float g_y   [(size_t)MTOK * Dq];
__device__ __align__(256) float g_cos [Lq * 32];
__device__ __align__(256) float g_sin [Lq * 32];
// fp16 operands / intermediates
__device__ __align__(256) __half g_xh [(size_t)MTOK * Dq];
__device__ __align__(256) __half g_ah [(size_t)MTOK * Dq];    // attn in fp16 (gemm2 A)
__device__ __align__(256) __half g_wh1[(size_t)NQKV * Dq];
__device__ __align__(256) __half g_wh2[(size_t)Dq * Dq];
__device__ __align__(256) __half g_qfh[(size_t)MTOK * Dq];    // qf, head-major [bh][l][64]
__device__ __align__(256) __half g_kfh[(size_t)MTOK * Dq];    // kf, head-major [bh][l][64]
__device__ __align__(256) __half g_vkh[64 * 64 * DHq];        // vk rows 0..63, fp16 [bh][p][d]

// ---------------------------------------------------------------------------
__device__ __forceinline__ uint32_t smem_u32(const void* p) {
    uint32_t a;
    asm("{ .reg .u64 t; cvta.to.shared.u64 t, %1; cvt.u32.u64 %0, t; }" : "=r"(a) : "l"(p));
    return a;
}
__device__ __forceinline__ void cp_async16(uint32_t dst, const void* src) {
    asm volatile("cp.async.cg.shared.global [%0], [%1], 16;" :: "r"(dst), "l"(src));
}
#define CP_COMMIT() asm volatile("cp.async.commit_group;" ::: "memory")
template <int N>
__device__ __forceinline__ void cp_wait() {
    asm volatile("cp.async.wait_group %0;" :: "n"(N) : "memory");
}
__device__ __forceinline__ void ldm_x4(uint32_t* r, uint32_t addr) {
    asm volatile("ldmatrix.sync.aligned.m8n8.x4.shared.b16 {%0,%1,%2,%3}, [%4];"
                 : "=r"(r[0]), "=r"(r[1]), "=r"(r[2]), "=r"(r[3]) : "r"(addr));
}
__device__ __forceinline__ void ldm_x4t(uint32_t* r, uint32_t addr) {
    asm volatile("ldmatrix.sync.aligned.m8n8.x4.trans.shared.b16 {%0,%1,%2,%3}, [%4];"
                 : "=r"(r[0]), "=r"(r[1]), "=r"(r[2]), "=r"(r[3]) : "r"(addr));
}
__device__ __forceinline__ void mma_f16(float* c, const uint32_t* a, const uint32_t* b) {
    asm volatile(
        "mma.sync.aligned.m16n8k16.row.col.f32.f16.f16.f32 "
        "{%0,%1,%2,%3}, {%4,%5,%6,%7}, {%8,%9}, {%0,%1,%2,%3};"
        : "+f"(c[0]), "+f"(c[1]), "+f"(c[2]), "+f"(c[3])
        : "r"(a[0]), "r"(a[1]), "r"(a[2]), "r"(a[3]), "r"(b[0]), "r"(b[1]));
}

// ---------------------------------------------------------------------------
// K0: fused prep — rope tables + three fp32->fp16 conversions, grid-partitioned.
// ---------------------------------------------------------------------------
__device__ __forceinline__ void conv4(const float* __restrict__ s,
                                      __half* __restrict__ d, int i) {
    float4 v = ((const float4*)s)[i];
    ((__half2*)d)[2*i]   = __floats2half2_rn(v.x, v.y);
    ((__half2*)d)[2*i+1] = __floats2half2_rn(v.z, v.w);
}
#define NB_ROPE 512
#define NB_X    16384
#define NB_W1   3072
#define NB_W2   1024
__global__ __launch_bounds__(256) void prep_fused_k(
    const float* __restrict__ x, const float* __restrict__ W1,
    const float* __restrict__ W2,
    __half* __restrict__ xh, __half* __restrict__ wh1, __half* __restrict__ wh2)
{
    const int bid = blockIdx.x;
    const int tid = threadIdx.x;
    if (bid < NB_ROPE) {
        int idx = bid * 256 + tid;
        int l = idx >> 5, j = idx & 31;
        float inv_freq = expf(-(float)j * (9.210340371976184f / 32.0f));
        float ang = (float)l * inv_freq;
        g_cos[idx] = cosf(ang);
        g_sin[idx] = sinf(ang);
    } else if (bid < NB_ROPE + NB_X) {
        conv4(x, xh, (bid - NB_ROPE) * 256 + tid);
    } else if (bid < NB_ROPE + NB_X + NB_W1) {
        conv4(W1, wh1, (bid - NB_ROPE - NB_X) * 256 + tid);
    } else {
        conv4(W2, wh2, (bid - NB_ROPE - NB_X - NB_W1) * 256 + tid);
    }
}

// ---------------------------------------------------------------------------
// HMMA GEMM (R9-frozen): C[m,n] = sum_k A[m,k]*B[n,k] + bias[n], K = 1024.
// ---------------------------------------------------------------------------
#define BKS     32
#define NSLAB   32
#define PITCH   80
#define TILEB   (128 * PITCH)
#define OFF_B   TILEB
#define STAGE   (2 * TILEB)
#define NSTG    4

__global__ __launch_bounds__(256, 2)
void gemm_hmma3_k(const __half* __restrict__ A, const __half* __restrict__ B,
                  const float* __restrict__ bias, float* __restrict__ C, int N)
{
    extern __shared__ __align__(16) char sm[];
    const uint32_t smb = smem_u32(sm);
    const int tid  = threadIdx.x;
    const int wid  = tid >> 5, lane = tid & 31;
    const int wm   = wid & 3, wn = wid >> 2;
    const int g    = lane >> 2, t = lane & 3;
    const int m0   = blockIdx.y * 128;
    const int n0   = blockIdx.x * 128;

    float acc[2][8][4];
#pragma unroll
    for (int mf = 0; mf < 2; ++mf)
#pragma unroll
        for (int nf = 0; nf < 8; ++nf)
#pragma unroll
            for (int e = 0; e < 4; ++e) acc[mf][nf][e] = 0.0f;

    const int crow = tid >> 2;
    const int c16  = tid & 3;
    auto load_slab = [&](int ks, int st) {
        uint32_t base = smb + st * STAGE;
#pragma unroll
        for (int j = 0; j < 2; ++j) {
            int row = crow + j * 64;
            uint32_t d = base + row * PITCH + c16 * 16;
            cp_async16(d,         A + (size_t)(m0 + row) * 1024 + ks * BKS + c16 * 8);
            cp_async16(d + OFF_B, B + (size_t)(n0 + row) * 1024 + ks * BKS + c16 * 8);
        }
        CP_COMMIT();
    };

    const int quad = lane >> 3, r8 = lane & 7;
    const uint32_t aoff = (uint32_t)((wm * 32 + (quad & 1) * 8 + r8) * PITCH + (quad >> 1) * 16);
    const uint32_t boff = (uint32_t)((wn * 64 + (quad >> 1) * 8 + r8) * PITCH + (quad & 1) * 16);

    load_slab(0, 0);
    load_slab(1, 1);
    load_slab(2, 2);

#pragma unroll 1
    for (int i = 0; i < NSLAB; ++i) {
        cp_wait<2>();
        __syncthreads();
        if (i + 3 < NSLAB) load_slab(i + 3, (i + 3) & 3);
        else CP_COMMIT();
        const uint32_t st = smb + (uint32_t)(i & 3) * STAGE;
#pragma unroll
        for (int kk = 0; kk < 2; ++kk) {
            uint32_t a[2][4];
            ldm_x4(a[0], st + aoff + kk * 32);
            ldm_x4(a[1], st + aoff + kk * 32 + 16 * PITCH);
            const uint32_t bb = st + OFF_B + boff + kk * 32;
#pragma unroll
            for (int nf2 = 0; nf2 < 4; ++nf2) {
                uint32_t b[4];
                ldm_x4(b, bb + nf2 * (16 * PITCH));
                mma_f16(acc[0][2*nf2],   a[0], b);
                mma_f16(acc[0][2*nf2+1], a[0], b + 2);
                mma_f16(acc[1][2*nf2],   a[1], b);
                mma_f16(acc[1][2*nf2+1], a[1], b + 2);
            }
        }
    }

#pragma unroll
    for (int mf = 0; mf < 2; ++mf) {
        int row = m0 + wm * 32 + mf * 16 + g;
#pragma unroll
        for (int nf = 0; nf < 8; ++nf) {
            int col = n0 + wn * 64 + nf * 8 + 2 * t;
            float b0 = bias[col], b1 = bias[col + 1];
            float2 o0 = make_float2(acc[mf][nf][0] + b0, acc[mf][nf][1] + b1);
            float2 o1 = make_float2(acc[mf][nf][2] + b0, acc[mf][nf][3] + b1);
            *(float2*)(C + (size_t)row * N + col)       = o0;
            *(float2*)(C + (size_t)(row + 8) * N + col) = o1;
        }
    }
}

// ---------------------------------------------------------------------------
// K2: qk_prep, warp-per-token (no block barriers).
// ---------------------------------------------------------------------------
__global__ __launch_bounds__(256) void qk_prep_k(const float* __restrict__ gq,
                                                 const float* __restrict__ gk)
{
    const int warp = threadIdx.x >> 5, lane = threadIdx.x & 31;
    const int t = blockIdx.x * 8 + warp;
    const int b = t >> 12;
    const int l = t & (Lq - 1);
    const float* row = g_qkv + (size_t)t * NQKV;
    float4 qv[8], kv[8];
    float sq = 0.0f, sk = 0.0f;
#pragma unroll
    for (int s = 0; s < 8; ++s) {
        qv[s] = *(const float4*)(row + lane * 4 + s * 128);
        kv[s] = *(const float4*)(row + Dq + lane * 4 + s * 128);
        sq += qv[s].x*qv[s].x + qv[s].y*qv[s].y + qv[s].z*qv[s].z + qv[s].w*qv[s].w;
        sk += kv[s].x*kv[s].x + kv[s].y*kv[s].y + kv[s].z*kv[s].z + kv[s].w*kv[s].w;
    }
#pragma unroll
    for (int o = 16; o > 0; o >>= 1) {
        sq += __shfl_xor_sync(0xffffffffu, sq, o);
        sk += __shfl_xor_sync(0xffffffffu, sk, o);
    }
    const float scq = rsqrtf(sq * (1.0f / 1024.0f) + RMSEPS);
    const float sck = rsqrtf(sk * (1.0f / 1024.0f) + RMSEPS);
#pragma unroll
    for (int s = 0; s < 8; ++s) {
        const int c0 = lane * 4 + s * 128;
        float4 gq4 = *(const float4*)(gq + c0);
        float4 gk4 = *(const float4*)(gk + c0);
        float qe[4] = {qv[s].x*scq*gq4.x, qv[s].y*scq*gq4.y, qv[s].z*scq*gq4.z, qv[s].w*scq*gq4.w};
        float ke[4] = {kv[s].x*sck*gk4.x, kv[s].y*sck*gk4.y, kv[s].z*sck*gk4.z, kv[s].w*sck*gk4.w};
#pragma unroll
        for (int p = 0; p < 2; ++p) {
            int d = (c0 + 2 * p) & 63;
            int j = d >> 1;
            float c = g_cos[l * 32 + j];
            float sn = g_sin[l * 32 + j];
            float q0 = qe[2*p], q1 = qe[2*p + 1];
            qe[2*p]     = q0 * c - q1 * sn;
            qe[2*p + 1] = q0 * sn + q1 * c;
            float k0 = ke[2*p], k1 = ke[2*p + 1];
            ke[2*p]     = k0 * c - k1 * sn;
            ke[2*p + 1] = k0 * sn + k1 * c;
        }
        const int h = c0 >> 6, d0 = c0 & 63;
        const size_t off = (((size_t)(b * Hq + h) * Lq) + l) * DHq + d0;
        uint2 qo, ko;
        *(__half2*)&qo.x = __floats2half2_rn(fmaxf(qe[0],0.f), fmaxf(qe[1],0.f));
        *(__half2*)&qo.y = __floats2half2_rn(fmaxf(qe[2],0.f), fmaxf(qe[3],0.f));
        *(__half2*)&ko.x = __floats2half2_rn(fmaxf(ke[0],0.f), fmaxf(ke[1],0.f));
        *(__half2*)&ko.y = __floats2half2_rn(fmaxf(ke[2],0.f), fmaxf(ke[3],0.f));
        *(uint2*)(g_qfh + off) = qo;
        *(uint2*)(g_kfh + off) = ko;
    }
}

// ---------------------------------------------------------------------------
// K3: vk partials via HMMA. CTA = (bh, chunk of 256 tokens).
// vk[p,d] = sum_l v[l,p]*kf[l,d]: A = v^T (ldmatrix.trans), B = kf^T (trans).
// v converted fp32->fp16 at STS; den kept as scalar fp32 path.
// 8 warps = 4(p16) x 2(d32); K = 32 per sub, 8 subs. Double-buffered smem.
// ---------------------------------------------------------------------------
#define VKB 72   // smem pitch in halves (144 B, 16B-aligned rows, conflict-free)
__global__ __launch_bounds__(256) void vk_accum_k() {
    const int bh = blockIdx.x;
    const int chunk = blockIdx.y;
    const int b = bh >> 4, h = bh & 15;
    const int tid = threadIdx.x;
    __shared__ __align__(16) __half kf_h[2][32 * VKB];
    __shared__ __align__(16) __half v_h [2][32 * VKB];

    const int l0 = chunk * (Lq / NCHUNK);
    const int tok0 = b * Lq + l0;
    const int r0 = tid >> 4;            // 0..15
    const int c4 = (tid & 15) << 2;     // 0..60
    const int lr  = tid >> 3;           // 0..31
    const int lc8 = (tid & 7) << 3;     // 0..56

    uint4 kraw;
    float4 vst0, vst1;
    auto ldg_sub = [&](int sub) {
        kraw = *(const uint4*)(g_kfh + ((size_t)bh * Lq + l0 + sub * 32 + lr) * DHq + lc8);
        vst0 = *(const float4*)(g_qkv + (size_t)(tok0 + sub * 32 + r0) * NQKV + 2 * Dq + h * DHq + c4);
        vst1 = *(const float4*)(g_qkv + (size_t)(tok0 + sub * 32 + r0 + 16) * NQKV + 2 * Dq + h * DHq + c4);
    };
    ldg_sub(0);

    // MMA geometry
    const int wid = tid >> 5, lane = tid & 31;
    const int wm = wid & 3, dn = wid >> 2;     // p-block 16, d-block 32
    const int quad = lane >> 3, r8 = lane & 7;
    const int g = lane >> 2, t = lane & 3;
    const int p0 = wm * 16, d0 = dn * 32;
    const uint32_t vbase = smem_u32(v_h);
    const uint32_t kbase = smem_u32(kf_h);
    // A (v^T): quad&1 -> p+8 (col), quad>>1 -> l+8 (row)
    const uint32_t aoff = (uint32_t)((((quad >> 1) * 8 + r8) * VKB + p0 + (quad & 1) * 8) * 2);
    // B (kf^T): quad&1 -> l+8 (row), quad>>1 -> d+8 (col)
    const uint32_t boff = (uint32_t)((((quad & 1) * 8 + r8) * VKB + d0 + (quad >> 1) * 8) * 2);

    float acc[4][4];
#pragma unroll
    for (int i = 0; i < 4; ++i)
#pragma unroll
        for (int j = 0; j < 4; ++j) acc[i][j] = 0.0f;
    float den = 0.0f;   // valid for tid < 64 (d = tid)

    const int NSUB = (Lq / NCHUNK) / 32;   // 8
#pragma unroll 1
    for (int sub = 0; sub < NSUB; ++sub) {
        const int bufi = sub & 1;
        {
            *(uint4*)&kf_h[bufi][lr * VKB + lc8] = kraw;
            uint2 vh0, vh1;
            *(__half2*)&vh0.x = __floats2half2_rn(vst0.x, vst0.y);
            *(__half2*)&vh0.y = __floats2half2_rn(vst0.z, vst0.w);
            *(__half2*)&vh1.x = __floats2half2_rn(vst1.x, vst1.y);
            *(__half2*)&vh1.y = __floats2half2_rn(vst1.z, vst1.w);
            *(uint2*)&v_h[bufi][r0 * VKB + c4]        = vh0;
            *(uint2*)&v_h[bufi][(r0 + 16) * VKB + c4] = vh1;
        }
        __syncthreads();
        if (sub + 1 < NSUB) ldg_sub(sub + 1);
        const uint32_t vB = vbase + (uint32_t)bufi * (32 * VKB * 2);
        const uint32_t kB = kbase + (uint32_t)bufi * (32 * VKB * 2);
#pragma unroll
        for (int ks2 = 0; ks2 < 2; ++ks2) {     // two K=16 steps per sub
            uint32_t a[4];
            ldm_x4t(a, vB + aoff + ks2 * (16 * VKB * 2));
#pragma unroll
            for (int nb = 0; nb < 2; ++nb) {
                uint32_t bf[4];
                ldm_x4t(bf, kB + boff + nb * 32 + ks2 * (16 * VKB * 2));   // nb*16 halves
                mma_f16(acc[2*nb],     a, bf);
                mma_f16(acc[2*nb + 1], a, bf + 2);
            }
        }
        if (tid < 64) {
#pragma unroll 8
            for (int l = 0; l < 32; ++l)
                den += __half2float(kf_h[bufi][l * VKB + tid]);
        }
        // no trailing barrier: next iteration writes the other buffer.
    }
    float* dst = g_vkp + (size_t)chunk * (64 * 65 * 64) + bh * (65 * 64);
#pragma unroll
    for (int nb = 0; nb < 4; ++nb) {
        const int d = d0 + nb * 8 + 2 * t;
        *(float2*)(dst + (p0 + g) * 64 + d)     = make_float2(acc[nb][0], acc[nb][1]);
        *(float2*)(dst + (p0 + g + 8) * 64 + d) = make_float2(acc[nb][2], acc[nb][3]);
    }
    if (tid < 64) dst[64 * 64 + tid] = den;
}

// K4: deterministic reduce; num rows -> fp16 g_vkh, den row -> fp32 g_vkden.
__global__ void vk_reduce_k() {
    int i = blockIdx.x * 256 + threadIdx.x;
    if (i >= 64 * 65 * 64) return;
    float s = 0.0f;
#pragma unroll
    for (int c = 0; c < NCHUNK; ++c) s += g_vkp[(size_t)c * (64 * 65 * 64) + i];
    const int bh = i / (65 * 64);
    const int rem = i - bh * (65 * 64);
    const int p = rem >> 6, d = rem & 63;
    if (p < 64) g_vkh[(size_t)bh * 4096 + p * 64 + d] = __float2half_rn(s);
    else        g_vkden[bh * 64 + d] = s;
}

// ---------------------------------------------------------------------------
// K5: attn via HMMA. CTA = (bh, 64-token tile).
// ---------------------------------------------------------------------------
#define QP 72   // smem pitch in halves (144 B)
__global__ __launch_bounds__(256) void attn_hmma_k() {
    const int bh = blockIdx.x;
    const int lt = blockIdx.y;
    const int b = bh >> 4, h = bh & 15;
    const int tid = threadIdx.x;
    __shared__ __align__(16) __half qf_h[64 * QP];
    __shared__ __align__(16) __half vk_h[64 * QP];
    __shared__ float den_row[64];
    __shared__ float den_s[64];

    {
        const __half* qsrc = g_qfh + ((size_t)bh * Lq + lt * 64) * DHq;
        const __half* vsrc = g_vkh + (size_t)bh * 4096;
#pragma unroll
        for (int j = 0; j < 2; ++j) {
            int chunk = tid + j * 256;
            int r = chunk >> 3, c8 = (chunk & 7) << 3;
            *(uint4*)&qf_h[r * QP + c8] = *(const uint4*)(qsrc + r * 64 + c8);
            *(uint4*)&vk_h[r * QP + c8] = *(const uint4*)(vsrc + r * 64 + c8);
        }
        if (tid < 64) den_row[tid] = g_vkden[bh * 64 + tid];
    }
    __syncthreads();

    if (tid < 64) {
        float d = 0.0f;
#pragma unroll
        for (int k = 0; k < 64; ++k)
            d = fmaf(den_row[k], __half2float(qf_h[tid * QP + k]), d);
        den_s[tid] = d;
    }

    const int wid = tid >> 5, lane = tid & 31;
    const int wm = wid & 3, wn = wid >> 2;
    const int quad = lane >> 3, r8 = lane & 7;
    const int g = lane >> 2, t = lane & 3;
    const uint32_t qb = smem_u32(qf_h);
    const uint32_t vb = smem_u32(vk_h);
    const uint32_t aoff = (uint32_t)((wm * 16 + (quad & 1) * 8 + r8) * (QP * 2) + (quad >> 1) * 16);
    const uint32_t boff = (uint32_t)((wn * 32 + (quad >> 1) * 8 + r8) * (QP * 2) + (quad & 1) * 16);
    float acc[4][4];
#pragma unroll
    for (int i = 0; i < 4; ++i)
#pragma unroll
        for (int j = 0; j < 4; ++j) acc[i][j] = 0.0f;
#pragma unroll
    for (int kk = 0; kk < 4; ++kk) {
        uint32_t a[4];
        ldm_x4(a, qb + aoff + kk * 32);
#pragma unroll
        for (int nf2 = 0; nf2 < 2; ++nf2) {
            uint32_t bfr[4];
            ldm_x4(bfr, vb + boff + nf2 * (16 * QP * 2) + kk * 32);
            mma_f16(acc[2*nf2],     a, bfr);
            mma_f16(acc[2*nf2 + 1], a, bfr + 2);
        }
    }
    __syncthreads();

#pragma unroll
    for (int nf = 0; nf < 4; ++nf) {
        const int p = wn * 32 + nf * 8 + 2 * t;
        const int tok0 = wm * 16 + g;
        const float d0 = den_s[tok0] + EPSLIN;
        const float d1 = den_s[tok0 + 8] + EPSLIN;
        __half2 o0 = __floats2half2_rn(acc[nf][0] / d0, acc[nf][1] / d0);
        __half2 o1 = __floats2half2_rn(acc[nf][2] / d1, acc[nf][3] / d1);
        *(__half2*)(g_ah + (size_t)(b * Lq + lt * 64 + tok0) * Dq + h * DHq + p)     = o0;
        *(__half2*)(g_ah + (size_t)(b * Lq + lt * 64 + tok0 + 8) * Dq + h * DHq + p) = o1;
    }
}

// ---------------------------------------------------------------------------
// K7: final rmsnorm, warp-per-token.
// ---------------------------------------------------------------------------
__global__ __launch_bounds__(256) void out_rms_k(const float* __restrict__ gout,
                                                 float* __restrict__ out)
{
    const int warp = threadIdx.x >> 5, lane = threadIdx.x & 31;
    const int t = blockIdx.x * 8 + warp;
    const float* row = g_y + (size_t)t * Dq;
    float4 y[8];
    float ss = 0.0f;
#pragma unroll
    for (int s = 0; s < 8; ++s) {
        y[s] = *(const float4*)(row + lane * 4 + s * 128);
        ss += y[s].x*y[s].x + y[s].y*y[s].y + y[s].z*y[s].z + y[s].w*y[s].w;
    }
#pragma unroll
    for (int o = 16; o > 0; o >>= 1) ss += __shfl_xor_sync(0xffffffffu, ss, o);
    const float sc = rsqrtf(ss * (1.0f / 1024.0f) + RMSEPS);
#pragma unroll
    for (int s = 0; s < 8; ++s) {
        const int c0 = lane * 4 + s * 128;
        float4 gg = *(const float4*)(gout + c0);
        float4 o4;
        o4.x = y[s].x * sc * gg.x;
        o4.y = y[s].y * sc * gg.y;
        o4.z = y[s].z * sc * gg.z;
        o4.w = y[s].w * sc * gg.w;
        *(float4*)(out + (size_t)t * Dq + c0) = o4;
    }
}

// ---------------------------------------------------------------------------
extern "C" void kernel_launch(void* const* d_in, const int* in_sizes, int n_in,
                              void* d_out, int out_size) {
    (void)in_sizes; (void)n_in; (void)out_size;
    const float* x    = (const float*)d_in[0];
    const float* Wqkv = (const float*)d_in[1];
    const float* bqkv = (const float*)d_in[2];
    const float* gq   = (const float*)d_in[3];
    const float* gk   = (const float*)d_in[4];
    const float* Wout = (const float*)d_in[5];
    const float* bout = (const float*)d_in[6];
    const float* gout = (const float*)d_in[7];
    float* out = (float*)d_out;

    float *qkv_p, *y_p;
    __half *xh, *ah, *wh1, *wh2;
    cudaGetSymbolAddress((void**)&qkv_p, g_qkv);
    cudaGetSymbolAddress((void**)&y_p,   g_y);
    cudaGetSymbolAddress((void**)&xh,  g_xh);
    cudaGetSymbolAddress((void**)&ah,  g_ah);
    cudaGetSymbolAddress((void**)&wh1, g_wh1);
    cudaGetSymbolAddress((void**)&wh2, g_wh2);

    const int DSMEM = NSTG * STAGE;   // 81920
    cudaFuncSetAttribute(gemm_hmma3_k, cudaFuncAttributeMaxDynamicSharedMemorySize, DSMEM);

    prep_fused_k<<<NB_ROPE + NB_X + NB_W1 + NB_W2, 256>>>(x, Wqkv, Wout, xh, wh1, wh2); // 0
    gemm_hmma3_k<<<dim3(NQKV / 128, MTOK / 128), 256, DSMEM>>>(                          // 1
        xh, wh1, bqkv, qkv_p, NQKV);
    qk_prep_k<<<MTOK / 8, 256>>>(gq, gk);                                                // 2
    vk_accum_k<<<dim3(64, NCHUNK), 256>>>();                                             // 3 (profiled)
    vk_reduce_k<<<(64 * 65 * 64 + 255) / 256, 256>>>();
    attn_hmma_k<<<dim3(64, 64), 256>>>();
    gemm_hmma3_k<<<dim3(Dq / 128, MTOK / 128), 256, DSMEM>>>(
        ah, wh2, bout, y_p, Dq);
    out_rms_k<<<MTOK / 8, 256>>>(gout, out);
}